// round 2
// baseline (speedup 1.0000x reference)
#include <cuda_runtime.h>
#include <math.h>
#include <stdint.h>

// Problem constants
#define BB    16
#define CC    384
#define NTOK  1024          // 32*32
#define MTOT  (BB*NTOK)     // 16384 tokens
#define NHEAD 8
#define DH    48

// ---------------- scratch (no allocations allowed) ----------------
__device__ float g_t  [MTOT*CC];        // token-major activations [m][c]
__device__ float g_xn [MTOT*CC];        // layernorm output (reused for both LNs)
__device__ float g_qkv[MTOT*3*CC];      // qkv projection
__device__ float g_o  [MTOT*CC];        // attention output
__device__ float g_h  [MTOT*4*CC];      // mlp hidden

// ---------------- kernel 1: depthwise conv 3x3 + pos bias + layout change ----
__global__ void conv_prep_kernel(const float* __restrict__ x,
                                 const float* __restrict__ pw,
                                 const float* __restrict__ pb,
                                 float* __restrict__ t) {
    int idx = blockIdx.x * blockDim.x + threadIdx.x;
    if (idx >= BB * CC * NTOK) return;
    int w = idx & 31;
    int h = (idx >> 5) & 31;
    int c = (idx >> 10) % CC;
    int b = idx / (CC * NTOK);
    const float* xp = x + ((size_t)(b * CC + c) << 10);
    const float* k  = pw + c * 9;
    float acc = 0.f;
    #pragma unroll
    for (int dh = -1; dh <= 1; dh++) {
        int hh = h + dh;
        if (hh < 0 || hh > 31) continue;
        #pragma unroll
        for (int dw = -1; dw <= 1; dw++) {
            int ww = w + dw;
            if (ww < 0 || ww > 31) continue;
            acc += xp[hh * 32 + ww] * k[(dh + 1) * 3 + (dw + 1)];
        }
    }
    float v = xp[h * 32 + w] + acc + pb[c];
    t[(size_t)(b * NTOK + h * 32 + w) * CC + c] = v;
}

// ---------------- kernel 2: LayerNorm (one warp per row of 384) --------------
__global__ void ln_kernel(const float* __restrict__ in,
                          const float* __restrict__ g,
                          const float* __restrict__ bta,
                          float* __restrict__ out) {
    int warp = threadIdx.x >> 5;
    int lane = threadIdx.x & 31;
    int row  = blockIdx.x * 8 + warp;
    const float4* ip = (const float4*)(in + (size_t)row * CC);
    float4 v[3];
    #pragma unroll
    for (int i = 0; i < 3; i++) v[i] = ip[lane + 32 * i];
    float s = 0.f;
    #pragma unroll
    for (int i = 0; i < 3; i++) s += v[i].x + v[i].y + v[i].z + v[i].w;
    #pragma unroll
    for (int o = 16; o; o >>= 1) s += __shfl_xor_sync(0xffffffffu, s, o);
    float mu = s * (1.0f / CC);
    float q = 0.f;
    #pragma unroll
    for (int i = 0; i < 3; i++) {
        float a = v[i].x - mu, b2 = v[i].y - mu, c2 = v[i].z - mu, d2 = v[i].w - mu;
        q += a * a + b2 * b2 + c2 * c2 + d2 * d2;
    }
    #pragma unroll
    for (int o = 16; o; o >>= 1) q += __shfl_xor_sync(0xffffffffu, q, o);
    float r = rsqrtf(q * (1.0f / CC) + 1e-5f);
    float4* op = (float4*)(out + (size_t)row * CC);
    const float4* gp = (const float4*)g;
    const float4* bp = (const float4*)bta;
    #pragma unroll
    for (int i = 0; i < 3; i++) {
        float4 gg = gp[lane + 32 * i];
        float4 bb = bp[lane + 32 * i];
        float4 o4;
        o4.x = (v[i].x - mu) * r * gg.x + bb.x;
        o4.y = (v[i].y - mu) * r * gg.y + bb.y;
        o4.z = (v[i].z - mu) * r * gg.z + bb.z;
        o4.w = (v[i].w - mu) * r * gg.w + bb.w;
        op[lane + 32 * i] = o4;
    }
}

// ---------------- tf32 helpers ---------------------------------------------
__device__ __forceinline__ uint32_t f2tf(float x) {
    uint32_t r;
    asm("cvt.rna.tf32.f32 %0, %1;" : "=r"(r) : "f"(x));
    return r;
}

__device__ __forceinline__ void mma_tf32(float c[4],
                                         uint32_t a0, uint32_t a1, uint32_t a2, uint32_t a3,
                                         uint32_t b0, uint32_t b1) {
    asm volatile(
        "mma.sync.aligned.m16n8k8.row.col.f32.tf32.tf32.f32 "
        "{%0,%1,%2,%3}, {%4,%5,%6,%7}, {%8,%9}, {%0,%1,%2,%3};\n"
        : "+f"(c[0]), "+f"(c[1]), "+f"(c[2]), "+f"(c[3])
        : "r"(a0), "r"(a1), "r"(a2), "r"(a3), "r"(b0), "r"(b1));
}

__device__ __forceinline__ float gelu_exact(float x) {
    return x * normcdff(x);
}

// ---------------- kernel 3: tf32 tensor-core GEMM ---------------------------
// C[M,N] = epi(A[M,K] @ B[K,N] + bias). BM=128 BN=128 BK=32, 256 threads,
// 8 warps in 4(m) x 2(n); warp tile 32x64 = 2 m-tiles x 8 n-tiles of m16n8k8.
#define ASTRIDE 36
#define BSTRIDE 136

template<bool RESID, bool GELU>
__global__ __launch_bounds__(256, 2)
void tgemm_kernel(const float* __restrict__ A, const float* __restrict__ Bm,
                  const float* __restrict__ bias, float* __restrict__ Cm,
                  int M, int N, int K) {
    __shared__ float As[128][ASTRIDE];   // [m][k], tf32 bit patterns
    __shared__ float Bs[32][BSTRIDE];    // [k][n], tf32 bit patterns

    int tid = threadIdx.x;
    int m0 = blockIdx.y * 128;
    int n0 = blockIdx.x * 128;

    int wid  = tid >> 5;
    int lane = tid & 31;
    int wm = (wid >> 1) * 32;
    int wn = (wid & 1) * 64;
    int g  = lane >> 2;
    int t0 = lane & 3;

    // global tile load indexing
    int ar = tid >> 3, ac = tid & 7;       // A: rows ar+32i, float4 at k=4*ac
    int br = tid >> 5, bc = tid & 31;      // B: rows br+8i, float4 at n=4*bc

    const float* Ap = A + (size_t)(m0 + ar) * K + ac * 4;
    const float* Bp = Bm + (size_t)br * N + n0 + bc * 4;

    float acc[2][8][4];
    #pragma unroll
    for (int mt = 0; mt < 2; mt++)
        #pragma unroll
        for (int nt = 0; nt < 8; nt++)
            #pragma unroll
            for (int i = 0; i < 4; i++) acc[mt][nt][i] = 0.f;

    float4 aR[4], bR[4];
    // prologue: load tile 0
    #pragma unroll
    for (int i = 0; i < 4; i++) aR[i] = *(const float4*)(Ap + (size_t)(32 * i) * K);
    #pragma unroll
    for (int i = 0; i < 4; i++) bR[i] = *(const float4*)(Bp + (size_t)(8 * i) * N);
    #pragma unroll
    for (int i = 0; i < 4; i++) {
        float4 v = aR[i];
        float* d = &As[ar + 32 * i][ac * 4];
        d[0] = __uint_as_float(f2tf(v.x)); d[1] = __uint_as_float(f2tf(v.y));
        d[2] = __uint_as_float(f2tf(v.z)); d[3] = __uint_as_float(f2tf(v.w));
    }
    #pragma unroll
    for (int i = 0; i < 4; i++) {
        float4 v = bR[i];
        float* d = &Bs[br + 8 * i][bc * 4];
        d[0] = __uint_as_float(f2tf(v.x)); d[1] = __uint_as_float(f2tf(v.y));
        d[2] = __uint_as_float(f2tf(v.z)); d[3] = __uint_as_float(f2tf(v.w));
    }
    __syncthreads();

    int nkt = K >> 5;
    for (int kt = 0; kt < nkt; kt++) {
        // prefetch next tile into registers while computing
        if (kt + 1 < nkt) {
            const float* Apn = Ap + (kt + 1) * 32;
            const float* Bpn = Bp + (size_t)((kt + 1) * 32) * N;
            #pragma unroll
            for (int i = 0; i < 4; i++) aR[i] = *(const float4*)(Apn + (size_t)(32 * i) * K);
            #pragma unroll
            for (int i = 0; i < 4; i++) bR[i] = *(const float4*)(Bpn + (size_t)(8 * i) * N);
        }

        #pragma unroll
        for (int kk = 0; kk < 32; kk += 8) {
            uint32_t a[2][4];
            #pragma unroll
            for (int mt = 0; mt < 2; mt++) {
                int r = wm + mt * 16 + g;
                a[mt][0] = __float_as_uint(As[r][kk + t0]);
                a[mt][1] = __float_as_uint(As[r + 8][kk + t0]);
                a[mt][2] = __float_as_uint(As[r][kk + t0 + 4]);
                a[mt][3] = __float_as_uint(As[r + 8][kk + t0 + 4]);
            }
            #pragma unroll
            for (int nt = 0; nt < 8; nt++) {
                int cn = wn + nt * 8 + g;
                uint32_t b0 = __float_as_uint(Bs[kk + t0][cn]);
                uint32_t b1 = __float_as_uint(Bs[kk + t0 + 4][cn]);
                mma_tf32(acc[0][nt], a[0][0], a[0][1], a[0][2], a[0][3], b0, b1);
                mma_tf32(acc[1][nt], a[1][0], a[1][1], a[1][2], a[1][3], b0, b1);
            }
        }
        __syncthreads();
        if (kt + 1 < nkt) {
            #pragma unroll
            for (int i = 0; i < 4; i++) {
                float4 v = aR[i];
                float* d = &As[ar + 32 * i][ac * 4];
                d[0] = __uint_as_float(f2tf(v.x)); d[1] = __uint_as_float(f2tf(v.y));
                d[2] = __uint_as_float(f2tf(v.z)); d[3] = __uint_as_float(f2tf(v.w));
            }
            #pragma unroll
            for (int i = 0; i < 4; i++) {
                float4 v = bR[i];
                float* d = &Bs[br + 8 * i][bc * 4];
                d[0] = __uint_as_float(f2tf(v.x)); d[1] = __uint_as_float(f2tf(v.y));
                d[2] = __uint_as_float(f2tf(v.z)); d[3] = __uint_as_float(f2tf(v.w));
            }
            __syncthreads();
        }
    }

    // epilogue
    #pragma unroll
    for (int mt = 0; mt < 2; mt++) {
        #pragma unroll
        for (int nt = 0; nt < 8; nt++) {
            int row = m0 + wm + mt * 16 + g;
            int col = n0 + wn + nt * 8 + 2 * t0;
            float2 bs = *(const float2*)(bias + col);
            float v0 = acc[mt][nt][0] + bs.x;
            float v1 = acc[mt][nt][1] + bs.y;
            float v2 = acc[mt][nt][2] + bs.x;
            float v3 = acc[mt][nt][3] + bs.y;
            if (GELU) {
                v0 = gelu_exact(v0); v1 = gelu_exact(v1);
                v2 = gelu_exact(v2); v3 = gelu_exact(v3);
            }
            float* cp0 = Cm + (size_t)row * N + col;
            float* cp1 = Cm + (size_t)(row + 8) * N + col;
            if (RESID) {
                float2 o0 = *(const float2*)cp0;
                float2 o1 = *(const float2*)cp1;
                v0 += o0.x; v1 += o0.y; v2 += o1.x; v3 += o1.y;
            }
            *(float2*)cp0 = make_float2(v0, v1);
            *(float2*)cp1 = make_float2(v2, v3);
        }
    }
}

// ---------------- kernel 4: flash attention (SIMT, unchanged) --------------
__global__ __launch_bounds__(256)
void attn_kernel(const float* __restrict__ qkv, float* __restrict__ o) {
    __shared__ float Qs[64][48];
    __shared__ float Ks[32][48];
    __shared__ float Vs[32][48];
    __shared__ float Ss[64][32];

    int tid = threadIdx.x;
    int bh  = blockIdx.y;
    int b   = bh >> 3, h = bh & 7;
    int q0  = blockIdx.x * 64;
    const float scale = 0.14433756729740643f; // 48^-0.5

    const float* qbase = qkv + (size_t)(b * NTOK + q0) * (3 * CC) + h * DH;
    for (int i = tid; i < 64 * 12; i += 256) {
        int r = i / 12, c4 = i % 12;
        float4 v = *(const float4*)(qbase + (size_t)r * (3 * CC) + c4 * 4);
        v.x *= scale; v.y *= scale; v.z *= scale; v.w *= scale;
        *(float4*)&Qs[r][c4 * 4] = v;
    }

    int rrow = tid >> 2;
    int l4   = tid & 3;
    float m_i = -1e30f, l_i = 0.f;
    float oacc[12];
    #pragma unroll
    for (int d = 0; d < 12; d++) oacc[d] = 0.f;

    int ty = tid >> 4, tx = tid & 15;

    const float* kbase = qkv + (size_t)(b * NTOK) * (3 * CC) + CC + h * DH;
    const float* vbase = kbase + CC;
    __syncthreads();

    for (int kt = 0; kt < 32; kt++) {
        int k0 = kt * 32;
        for (int i = tid; i < 768; i += 256) {
            int which = (i >= 384);
            int j = which ? i - 384 : i;
            int r = j / 12, c4 = j % 12;
            const float* src = (which ? vbase : kbase) + (size_t)(k0 + r) * (3 * CC) + c4 * 4;
            float4 v = *(const float4*)src;
            if (which) *(float4*)&Vs[r][c4 * 4] = v;
            else       *(float4*)&Ks[r][c4 * 4] = v;
        }
        __syncthreads();

        float s[4][2];
        #pragma unroll
        for (int i = 0; i < 4; i++) { s[i][0] = 0.f; s[i][1] = 0.f; }
        #pragma unroll
        for (int kk = 0; kk < 48; kk += 4) {
            float4 qv[4], kv2[2];
            #pragma unroll
            for (int i = 0; i < 4; i++) qv[i] = *(const float4*)&Qs[4 * ty + i][kk];
            #pragma unroll
            for (int j = 0; j < 2; j++) kv2[j] = *(const float4*)&Ks[2 * tx + j][kk];
            #pragma unroll
            for (int i = 0; i < 4; i++)
                #pragma unroll
                for (int j = 0; j < 2; j++)
                    s[i][j] += qv[i].x * kv2[j].x + qv[i].y * kv2[j].y +
                               qv[i].z * kv2[j].z + qv[i].w * kv2[j].w;
        }
        #pragma unroll
        for (int i = 0; i < 4; i++) {
            Ss[4 * ty + i][2 * tx + 0] = s[i][0];
            Ss[4 * ty + i][2 * tx + 1] = s[i][1];
        }
        __syncthreads();

        float4 p0 = *(const float4*)&Ss[rrow][l4 * 8];
        float4 p1 = *(const float4*)&Ss[rrow][l4 * 8 + 4];
        float tm = fmaxf(fmaxf(fmaxf(p0.x, p0.y), fmaxf(p0.z, p0.w)),
                         fmaxf(fmaxf(p1.x, p1.y), fmaxf(p1.z, p1.w)));
        tm = fmaxf(tm, __shfl_xor_sync(0xffffffffu, tm, 1));
        tm = fmaxf(tm, __shfl_xor_sync(0xffffffffu, tm, 2));
        float newm = fmaxf(m_i, tm);
        float alpha = __expf(m_i - newm);
        p0.x = __expf(p0.x - newm); p0.y = __expf(p0.y - newm);
        p0.z = __expf(p0.z - newm); p0.w = __expf(p0.w - newm);
        p1.x = __expf(p1.x - newm); p1.y = __expf(p1.y - newm);
        p1.z = __expf(p1.z - newm); p1.w = __expf(p1.w - newm);
        float rs = p0.x + p0.y + p0.z + p0.w + p1.x + p1.y + p1.z + p1.w;
        rs += __shfl_xor_sync(0xffffffffu, rs, 1);
        rs += __shfl_xor_sync(0xffffffffu, rs, 2);
        l_i = l_i * alpha + rs;
        m_i = newm;
        #pragma unroll
        for (int d = 0; d < 12; d++) oacc[d] *= alpha;
        *(float4*)&Ss[rrow][l4 * 8]     = p0;
        *(float4*)&Ss[rrow][l4 * 8 + 4] = p1;
        __syncwarp();

        #pragma unroll 4
        for (int j = 0; j < 32; j++) {
            float p = Ss[rrow][j];
            float4 v0 = *(const float4*)&Vs[j][l4 * 12];
            float4 v1 = *(const float4*)&Vs[j][l4 * 12 + 4];
            float4 v2 = *(const float4*)&Vs[j][l4 * 12 + 8];
            oacc[0] += p * v0.x; oacc[1] += p * v0.y; oacc[2]  += p * v0.z; oacc[3]  += p * v0.w;
            oacc[4] += p * v1.x; oacc[5] += p * v1.y; oacc[6]  += p * v1.z; oacc[7]  += p * v1.w;
            oacc[8] += p * v2.x; oacc[9] += p * v2.y; oacc[10] += p * v2.z; oacc[11] += p * v2.w;
        }
        __syncthreads();
    }

    float inv = 1.f / l_i;
    float* op = o + (size_t)(b * NTOK + q0 + rrow) * CC + h * DH + l4 * 12;
    float4 w0 = make_float4(oacc[0] * inv, oacc[1] * inv, oacc[2] * inv, oacc[3] * inv);
    float4 w1 = make_float4(oacc[4] * inv, oacc[5] * inv, oacc[6] * inv, oacc[7] * inv);
    float4 w2 = make_float4(oacc[8] * inv, oacc[9] * inv, oacc[10] * inv, oacc[11] * inv);
    *(float4*)(op + 0) = w0;
    *(float4*)(op + 4) = w1;
    *(float4*)(op + 8) = w2;
}

// ---------------- kernel 5: final transpose to NCHW -----------------------
__global__ void transpose_kernel(const float* __restrict__ t, float* __restrict__ out) {
    __shared__ float tile[32][33];
    int b  = blockIdx.z;
    int n0 = blockIdx.x * 32;
    int c0 = blockIdx.y * 32;
    int tx = threadIdx.x, ty = threadIdx.y;
    #pragma unroll
    for (int i = 0; i < 4; i++)
        tile[ty + 8 * i][tx] = t[(size_t)(b * NTOK + n0 + ty + 8 * i) * CC + c0 + tx];
    __syncthreads();
    #pragma unroll
    for (int i = 0; i < 4; i++)
        out[(size_t)(b * CC + c0 + ty + 8 * i) * NTOK + n0 + tx] = tile[tx][ty + 8 * i];
}

// ---------------- launch ----------------------------------------------------
extern "C" void kernel_launch(void* const* d_in, const int* in_sizes, int n_in,
                              void* d_out, int out_size) {
    const float* x     = (const float*)d_in[0];
    const float* pos_w = (const float*)d_in[1];
    const float* pos_b = (const float*)d_in[2];
    const float* g1    = (const float*)d_in[3];
    const float* b1    = (const float*)d_in[4];
    const float* wqkv  = (const float*)d_in[5];
    const float* bqkv  = (const float*)d_in[6];
    const float* wproj = (const float*)d_in[7];
    const float* bproj = (const float*)d_in[8];
    const float* g2    = (const float*)d_in[9];
    const float* b2    = (const float*)d_in[10];
    const float* w1    = (const float*)d_in[11];
    const float* bf1   = (const float*)d_in[12];
    const float* w2    = (const float*)d_in[13];
    const float* bf2   = (const float*)d_in[14];
    float* out = (float*)d_out;

    float *t, *xn, *qkv, *o, *hbuf;
    cudaGetSymbolAddress((void**)&t,    g_t);
    cudaGetSymbolAddress((void**)&xn,   g_xn);
    cudaGetSymbolAddress((void**)&qkv,  g_qkv);
    cudaGetSymbolAddress((void**)&o,    g_o);
    cudaGetSymbolAddress((void**)&hbuf, g_h);

    // 1) conv + pos bias -> t[m][c]
    {
        int total = BB * CC * NTOK;
        conv_prep_kernel<<<(total + 255) / 256, 256>>>(x, pos_w, pos_b, t);
    }
    // 2) LN1: t -> xn
    ln_kernel<<<MTOT / 8, 256>>>(t, g1, b1, xn);
    // 3) qkv = xn @ wqkv + bqkv
    tgemm_kernel<false, false><<<dim3(3 * CC / 128, MTOT / 128), 256>>>(
        xn, wqkv, bqkv, qkv, MTOT, 3 * CC, CC);
    // 4) attention -> o
    attn_kernel<<<dim3(NTOK / 64, BB * NHEAD), 256>>>(qkv, o);
    // 5) t += o @ wproj + bproj
    tgemm_kernel<true, false><<<dim3(CC / 128, MTOT / 128), 256>>>(
        o, wproj, bproj, t, MTOT, CC, CC);
    // 6) LN2: t -> xn
    ln_kernel<<<MTOT / 8, 256>>>(t, g2, b2, xn);
    // 7) h = gelu(xn @ w1 + bf1)
    tgemm_kernel<false, true><<<dim3(4 * CC / 128, MTOT / 128), 256>>>(
        xn, w1, bf1, hbuf, MTOT, 4 * CC, CC);
    // 8) t += h @ w2 + bf2
    tgemm_kernel<true, false><<<dim3(CC / 128, MTOT / 128), 256>>>(
        hbuf, w2, bf2, t, MTOT, CC, 4 * CC);
    // 9) transpose to NCHW
    transpose_kernel<<<dim3(NTOK / 32, CC / 32, BB), dim3(32, 8)>>>(t, out);
}

// round 5
// speedup vs baseline: 1.6136x; 1.6136x over previous
#include <cuda_runtime.h>
#include <math.h>
#include <stdint.h>

// Problem constants
#define BB    16
#define CC    384
#define NTOK  1024          // 32*32
#define MTOT  (BB*NTOK)     // 16384 tokens
#define NHEAD 8
#define DH    48

// ---------------- scratch (no allocations allowed) ----------------
__device__ float g_t  [MTOT*CC];        // token-major activations [m][c]
__device__ float g_xn [MTOT*CC];        // layernorm output (reused for both LNs)
__device__ float g_qkv[MTOT*3*CC];      // qkv projection
__device__ float g_o  [MTOT*CC];        // attention output
__device__ float g_h  [MTOT*4*CC];      // mlp hidden
// tf32-rounded weights (same [K][N] layout as inputs)
__device__ float g_wt [384*1152 + 384*384 + 384*1536 + 1536*384];

#define WT_QKV_OFF  0
#define WT_PROJ_OFF (384*1152)
#define WT_W1_OFF   (WT_PROJ_OFF + 384*384)
#define WT_W2_OFF   (WT_W1_OFF + 384*1536)

// ---------------- helpers ----------------------------------------------
__device__ __forceinline__ uint32_t f2tf(float x) {
    uint32_t r;
    asm("cvt.rna.tf32.f32 %0, %1;" : "=r"(r) : "f"(x));
    return r;
}
__device__ __forceinline__ float f2tf_f(float x) { return __uint_as_float(f2tf(x)); }

__device__ __forceinline__ uint32_t smem_u32(const void* p) {
    uint32_t a;
    asm("{ .reg .u64 t; cvta.to.shared.u64 t, %1; cvt.u32.u64 %0, t; }" : "=r"(a) : "l"(p));
    return a;
}

__device__ __forceinline__ void cp_async16(uint32_t dst, const void* src) {
    asm volatile("cp.async.ca.shared.global [%0], [%1], 16;" :: "r"(dst), "l"(src));
}
#define CP_COMMIT() asm volatile("cp.async.commit_group;" ::: "memory")
#define CP_WAIT(n)  asm volatile("cp.async.wait_group %0;" :: "n"(n) : "memory")

__device__ __forceinline__ void mma_tf32(float c[4],
                                         uint32_t a0, uint32_t a1, uint32_t a2, uint32_t a3,
                                         uint32_t b0, uint32_t b1) {
    asm volatile(
        "mma.sync.aligned.m16n8k8.row.col.f32.tf32.tf32.f32 "
        "{%0,%1,%2,%3}, {%4,%5,%6,%7}, {%8,%9}, {%0,%1,%2,%3};\n"
        : "+f"(c[0]), "+f"(c[1]), "+f"(c[2]), "+f"(c[3])
        : "r"(a0), "r"(a1), "r"(a2), "r"(a3), "r"(b0), "r"(b1));
}

__device__ __forceinline__ float gelu_exact(float x) { return x * normcdff(x); }

// ---------------- kernel 0: round weights to tf32 ---------------------------
__global__ void wround_kernel(const float* __restrict__ W, float* __restrict__ Wo, int n) {
    int i = blockIdx.x * blockDim.x + threadIdx.x;
    int stride = gridDim.x * blockDim.x;
    for (; i < n; i += stride) Wo[i] = f2tf_f(W[i]);
}

// ---------------- kernel 1: depthwise conv 3x3 + pos bias + layout change ----
__global__ void conv_prep_kernel(const float* __restrict__ x,
                                 const float* __restrict__ pw,
                                 const float* __restrict__ pb,
                                 float* __restrict__ t) {
    int idx = blockIdx.x * blockDim.x + threadIdx.x;
    if (idx >= BB * CC * NTOK) return;
    int w = idx & 31;
    int h = (idx >> 5) & 31;
    int c = (idx >> 10) % CC;
    int b = idx / (CC * NTOK);
    const float* xp = x + ((size_t)(b * CC + c) << 10);
    const float* k  = pw + c * 9;
    float acc = 0.f;
    #pragma unroll
    for (int dh = -1; dh <= 1; dh++) {
        int hh = h + dh;
        if (hh < 0 || hh > 31) continue;
        #pragma unroll
        for (int dw = -1; dw <= 1; dw++) {
            int ww = w + dw;
            if (ww < 0 || ww > 31) continue;
            acc += xp[hh * 32 + ww] * k[(dh + 1) * 3 + (dw + 1)];
        }
    }
    float v = xp[h * 32 + w] + acc + pb[c];
    t[(size_t)(b * NTOK + h * 32 + w) * CC + c] = v;
}

// ---------------- kernel 2: LayerNorm (rounds output to tf32) ---------------
__global__ void ln_kernel(const float* __restrict__ in,
                          const float* __restrict__ g,
                          const float* __restrict__ bta,
                          float* __restrict__ out) {
    int warp = threadIdx.x >> 5;
    int lane = threadIdx.x & 31;
    int row  = blockIdx.x * 8 + warp;
    const float4* ip = (const float4*)(in + (size_t)row * CC);
    float4 v[3];
    #pragma unroll
    for (int i = 0; i < 3; i++) v[i] = ip[lane + 32 * i];
    float s = 0.f;
    #pragma unroll
    for (int i = 0; i < 3; i++) s += v[i].x + v[i].y + v[i].z + v[i].w;
    #pragma unroll
    for (int o = 16; o; o >>= 1) s += __shfl_xor_sync(0xffffffffu, s, o);
    float mu = s * (1.0f / CC);
    float q = 0.f;
    #pragma unroll
    for (int i = 0; i < 3; i++) {
        float a = v[i].x - mu, b2 = v[i].y - mu, c2 = v[i].z - mu, d2 = v[i].w - mu;
        q += a * a + b2 * b2 + c2 * c2 + d2 * d2;
    }
    #pragma unroll
    for (int o = 16; o; o >>= 1) q += __shfl_xor_sync(0xffffffffu, q, o);
    float r = rsqrtf(q * (1.0f / CC) + 1e-5f);
    float4* op = (float4*)(out + (size_t)row * CC);
    const float4* gp = (const float4*)g;
    const float4* bp = (const float4*)bta;
    #pragma unroll
    for (int i = 0; i < 3; i++) {
        float4 gg = gp[lane + 32 * i];
        float4 bb = bp[lane + 32 * i];
        float4 o4;
        o4.x = f2tf_f((v[i].x - mu) * r * gg.x + bb.x);
        o4.y = f2tf_f((v[i].y - mu) * r * gg.y + bb.y);
        o4.z = f2tf_f((v[i].z - mu) * r * gg.z + bb.z);
        o4.w = f2tf_f((v[i].w - mu) * r * gg.w + bb.w);
        op[lane + 32 * i] = o4;
    }
}

// ---------------- kernel 3: tf32 mma.sync GEMM, cp.async double buffered -----
// C[M,N] = epi(A[M,K] @ B[K,N] + bias). BM=128 BN=128 BK=16, 256 threads,
// 8 warps 4(m)x2(n), warp tile 32x64 = 2x8 m16n8k8. A,B already tf32-rounded.
#define ASTR 20
#define BSTR 136

template<bool RESID, bool GELU, bool ROUND>
__global__ __launch_bounds__(256)
void tgemm_kernel(const float* __restrict__ A, const float* __restrict__ Bm,
                  const float* __restrict__ bias, float* __restrict__ Cm,
                  int M, int N, int K) {
    __shared__ float As[2][128][ASTR];
    __shared__ float Bs[2][16][BSTR];

    int tid = threadIdx.x;
    int m0 = blockIdx.y * 128;
    int n0 = blockIdx.x * 128;

    int wid  = tid >> 5;
    int lane = tid & 31;
    int wm = (wid >> 1) * 32;
    int wn = (wid & 1) * 64;
    int g  = lane >> 2;
    int t0 = lane & 3;

    // A fill: rows ar, ar+64; 4 floats at col (tid&3)*4
    int ar = tid >> 2, ac4 = (tid & 3) * 4;
    // B fill: row kr; 2 chunks at cols bc4, bc4+64
    int kr = tid >> 4, bc4 = (tid & 15) * 4;

    const float* ApG = A + (size_t)(m0 + ar) * K + ac4;
    const float* BpG = Bm + (size_t)kr * N + n0 + bc4;

    uint32_t sA0 = smem_u32(&As[0][ar][ac4]);
    uint32_t sA1 = smem_u32(&As[0][ar + 64][ac4]);
    uint32_t sB0 = smem_u32(&Bs[0][kr][bc4]);
    uint32_t sB1 = smem_u32(&Bs[0][kr][bc4 + 64]);
    const uint32_t bufA = sizeof(float) * 128 * ASTR;
    const uint32_t bufB = sizeof(float) * 16 * BSTR;

    float acc[2][8][4];
    #pragma unroll
    for (int mt = 0; mt < 2; mt++)
        #pragma unroll
        for (int nt = 0; nt < 8; nt++)
            #pragma unroll
            for (int i = 0; i < 4; i++) acc[mt][nt][i] = 0.f;

    int nkt = K >> 4;

    // prologue: stage tile 0 into buf 0
    cp_async16(sA0, ApG);
    cp_async16(sA1, ApG + (size_t)64 * K);
    cp_async16(sB0, BpG);
    cp_async16(sB1, BpG + 64);
    CP_COMMIT();

    for (int kt = 0; kt < nkt; kt++) {
        int buf = kt & 1;
        if (kt + 1 < nkt) {
            int nb = 1 - buf;
            const float* Ap = ApG + (kt + 1) * 16;
            const float* Bp = BpG + (size_t)((kt + 1) * 16) * N;
            cp_async16(sA0 + nb * bufA, Ap);
            cp_async16(sA1 + nb * bufA, Ap + (size_t)64 * K);
            cp_async16(sB0 + nb * bufB, Bp);
            cp_async16(sB1 + nb * bufB, Bp + 64);
            CP_COMMIT();
            CP_WAIT(1);
        } else {
            CP_WAIT(0);
        }
        __syncthreads();

        #pragma unroll
        for (int kk = 0; kk < 16; kk += 8) {
            uint32_t a[2][4];
            #pragma unroll
            for (int mt = 0; mt < 2; mt++) {
                int r = wm + mt * 16 + g;
                a[mt][0] = __float_as_uint(As[buf][r][kk + t0]);
                a[mt][1] = __float_as_uint(As[buf][r + 8][kk + t0]);
                a[mt][2] = __float_as_uint(As[buf][r][kk + t0 + 4]);
                a[mt][3] = __float_as_uint(As[buf][r + 8][kk + t0 + 4]);
            }
            #pragma unroll
            for (int nt = 0; nt < 8; nt++) {
                int cn = wn + nt * 8 + g;
                uint32_t b0 = __float_as_uint(Bs[buf][kk + t0][cn]);
                uint32_t b1 = __float_as_uint(Bs[buf][kk + t0 + 4][cn]);
                mma_tf32(acc[0][nt], a[0][0], a[0][1], a[0][2], a[0][3], b0, b1);
                mma_tf32(acc[1][nt], a[1][0], a[1][1], a[1][2], a[1][3], b0, b1);
            }
        }
        __syncthreads();
    }

    // epilogue
    #pragma unroll
    for (int mt = 0; mt < 2; mt++) {
        #pragma unroll
        for (int nt = 0; nt < 8; nt++) {
            int row = m0 + wm + mt * 16 + g;
            int col = n0 + wn + nt * 8 + 2 * t0;
            float2 bs = *(const float2*)(bias + col);
            float v0 = acc[mt][nt][0] + bs.x;
            float v1 = acc[mt][nt][1] + bs.y;
            float v2 = acc[mt][nt][2] + bs.x;
            float v3 = acc[mt][nt][3] + bs.y;
            if (GELU) {
                v0 = gelu_exact(v0); v1 = gelu_exact(v1);
                v2 = gelu_exact(v2); v3 = gelu_exact(v3);
            }
            float* cp0 = Cm + (size_t)row * N + col;
            float* cp1 = Cm + (size_t)(row + 8) * N + col;
            if (RESID) {
                float2 o0 = *(const float2*)cp0;
                float2 o1 = *(const float2*)cp1;
                v0 += o0.x; v1 += o0.y; v2 += o1.x; v3 += o1.y;
            }
            if (ROUND) {
                v0 = f2tf_f(v0); v1 = f2tf_f(v1);
                v2 = f2tf_f(v2); v3 = f2tf_f(v3);
            }
            *(float2*)cp0 = make_float2(v0, v1);
            *(float2*)cp1 = make_float2(v2, v3);
        }
    }
}

// ---------------- kernel 4: flash attention (SIMT; output rounded) ----------
__global__ __launch_bounds__(256)
void attn_kernel(const float* __restrict__ qkv, float* __restrict__ o) {
    __shared__ float Qs[64][48];
    __shared__ float Ks[32][48];
    __shared__ float Vs[32][48];
    __shared__ float Ss[64][32];

    int tid = threadIdx.x;
    int bh  = blockIdx.y;
    int b   = bh >> 3, h = bh & 7;
    int q0  = blockIdx.x * 64;
    const float scale = 0.14433756729740643f; // 48^-0.5

    const float* qbase = qkv + (size_t)(b * NTOK + q0) * (3 * CC) + h * DH;
    for (int i = tid; i < 64 * 12; i += 256) {
        int r = i / 12, c4 = i % 12;
        float4 v = *(const float4*)(qbase + (size_t)r * (3 * CC) + c4 * 4);
        v.x *= scale; v.y *= scale; v.z *= scale; v.w *= scale;
        *(float4*)&Qs[r][c4 * 4] = v;
    }

    int rrow = tid >> 2;
    int l4   = tid & 3;
    float m_i = -1e30f, l_i = 0.f;
    float oacc[12];
    #pragma unroll
    for (int d = 0; d < 12; d++) oacc[d] = 0.f;

    int ty = tid >> 4, tx = tid & 15;

    const float* kbase = qkv + (size_t)(b * NTOK) * (3 * CC) + CC + h * DH;
    const float* vbase = kbase + CC;
    __syncthreads();

    for (int kt = 0; kt < 32; kt++) {
        int k0 = kt * 32;
        for (int i = tid; i < 768; i += 256) {
            int which = (i >= 384);
            int j = which ? i - 384 : i;
            int r = j / 12, c4 = j % 12;
            const float* src = (which ? vbase : kbase) + (size_t)(k0 + r) * (3 * CC) + c4 * 4;
            float4 v = *(const float4*)src;
            if (which) *(float4*)&Vs[r][c4 * 4] = v;
            else       *(float4*)&Ks[r][c4 * 4] = v;
        }
        __syncthreads();

        float s[4][2];
        #pragma unroll
        for (int i = 0; i < 4; i++) { s[i][0] = 0.f; s[i][1] = 0.f; }
        #pragma unroll
        for (int kk = 0; kk < 48; kk += 4) {
            float4 qv[4], kv2[2];
            #pragma unroll
            for (int i = 0; i < 4; i++) qv[i] = *(const float4*)&Qs[4 * ty + i][kk];
            #pragma unroll
            for (int j = 0; j < 2; j++) kv2[j] = *(const float4*)&Ks[2 * tx + j][kk];
            #pragma unroll
            for (int i = 0; i < 4; i++)
                #pragma unroll
                for (int j = 0; j < 2; j++)
                    s[i][j] += qv[i].x * kv2[j].x + qv[i].y * kv2[j].y +
                               qv[i].z * kv2[j].z + qv[i].w * kv2[j].w;
        }
        #pragma unroll
        for (int i = 0; i < 4; i++) {
            Ss[4 * ty + i][2 * tx + 0] = s[i][0];
            Ss[4 * ty + i][2 * tx + 1] = s[i][1];
        }
        __syncthreads();

        float4 p0 = *(const float4*)&Ss[rrow][l4 * 8];
        float4 p1 = *(const float4*)&Ss[rrow][l4 * 8 + 4];
        float tm = fmaxf(fmaxf(fmaxf(p0.x, p0.y), fmaxf(p0.z, p0.w)),
                         fmaxf(fmaxf(p1.x, p1.y), fmaxf(p1.z, p1.w)));
        tm = fmaxf(tm, __shfl_xor_sync(0xffffffffu, tm, 1));
        tm = fmaxf(tm, __shfl_xor_sync(0xffffffffu, tm, 2));
        float newm = fmaxf(m_i, tm);
        float alpha = __expf(m_i - newm);
        p0.x = __expf(p0.x - newm); p0.y = __expf(p0.y - newm);
        p0.z = __expf(p0.z - newm); p0.w = __expf(p0.w - newm);
        p1.x = __expf(p1.x - newm); p1.y = __expf(p1.y - newm);
        p1.z = __expf(p1.z - newm); p1.w = __expf(p1.w - newm);
        float rs = p0.x + p0.y + p0.z + p0.w + p1.x + p1.y + p1.z + p1.w;
        rs += __shfl_xor_sync(0xffffffffu, rs, 1);
        rs += __shfl_xor_sync(0xffffffffu, rs, 2);
        l_i = l_i * alpha + rs;
        m_i = newm;
        #pragma unroll
        for (int d = 0; d < 12; d++) oacc[d] *= alpha;
        *(float4*)&Ss[rrow][l4 * 8]     = p0;
        *(float4*)&Ss[rrow][l4 * 8 + 4] = p1;
        __syncwarp();

        #pragma unroll 4
        for (int j = 0; j < 32; j++) {
            float p = Ss[rrow][j];
            float4 v0 = *(const float4*)&Vs[j][l4 * 12];
            float4 v1 = *(const float4*)&Vs[j][l4 * 12 + 4];
            float4 v2 = *(const float4*)&Vs[j][l4 * 12 + 8];
            oacc[0] += p * v0.x; oacc[1] += p * v0.y; oacc[2]  += p * v0.z; oacc[3]  += p * v0.w;
            oacc[4] += p * v1.x; oacc[5] += p * v1.y; oacc[6]  += p * v1.z; oacc[7]  += p * v1.w;
            oacc[8] += p * v2.x; oacc[9] += p * v2.y; oacc[10] += p * v2.z; oacc[11] += p * v2.w;
        }
        __syncthreads();
    }

    float inv = 1.f / l_i;
    float* op = o + (size_t)(b * NTOK + q0 + rrow) * CC + h * DH + l4 * 12;
    float4 w0 = make_float4(f2tf_f(oacc[0] * inv), f2tf_f(oacc[1] * inv),
                            f2tf_f(oacc[2] * inv), f2tf_f(oacc[3] * inv));
    float4 w1 = make_float4(f2tf_f(oacc[4] * inv), f2tf_f(oacc[5] * inv),
                            f2tf_f(oacc[6] * inv), f2tf_f(oacc[7] * inv));
    float4 w2 = make_float4(f2tf_f(oacc[8] * inv), f2tf_f(oacc[9] * inv),
                            f2tf_f(oacc[10] * inv), f2tf_f(oacc[11] * inv));
    *(float4*)(op + 0) = w0;
    *(float4*)(op + 4) = w1;
    *(float4*)(op + 8) = w2;
}

// ---------------- kernel 5: final transpose to NCHW -------------------------
__global__ void transpose_kernel(const float* __restrict__ t, float* __restrict__ out) {
    __shared__ float tile[32][33];
    int b  = blockIdx.z;
    int n0 = blockIdx.x * 32;
    int c0 = blockIdx.y * 32;
    int tx = threadIdx.x, ty = threadIdx.y;
    #pragma unroll
    for (int i = 0; i < 4; i++)
        tile[ty + 8 * i][tx] = t[(size_t)(b * NTOK + n0 + ty + 8 * i) * CC + c0 + tx];
    __syncthreads();
    #pragma unroll
    for (int i = 0; i < 4; i++)
        out[(size_t)(b * CC + c0 + ty + 8 * i) * NTOK + n0 + tx] = tile[tx][ty + 8 * i];
}

// ---------------- launch ----------------------------------------------------
extern "C" void kernel_launch(void* const* d_in, const int* in_sizes, int n_in,
                              void* d_out, int out_size) {
    const float* x     = (const float*)d_in[0];
    const float* pos_w = (const float*)d_in[1];
    const float* pos_b = (const float*)d_in[2];
    const float* g1    = (const float*)d_in[3];
    const float* b1    = (const float*)d_in[4];
    const float* wqkv  = (const float*)d_in[5];
    const float* bqkv  = (const float*)d_in[6];
    const float* wproj = (const float*)d_in[7];
    const float* bproj = (const float*)d_in[8];
    const float* g2    = (const float*)d_in[9];
    const float* b2    = (const float*)d_in[10];
    const float* w1    = (const float*)d_in[11];
    const float* bf1   = (const float*)d_in[12];
    const float* w2    = (const float*)d_in[13];
    const float* bf2   = (const float*)d_in[14];
    float* out = (float*)d_out;

    float *t, *xn, *qkv, *o, *hbuf, *wt;
    cudaGetSymbolAddress((void**)&t,    g_t);
    cudaGetSymbolAddress((void**)&xn,   g_xn);
    cudaGetSymbolAddress((void**)&qkv,  g_qkv);
    cudaGetSymbolAddress((void**)&o,    g_o);
    cudaGetSymbolAddress((void**)&hbuf, g_h);
    cudaGetSymbolAddress((void**)&wt,   g_wt);

    // 0) tf32-round weights (keeps mma inputs exactly representable)
    wround_kernel<<<512, 256>>>(wqkv,  wt + WT_QKV_OFF,  384 * 1152);
    wround_kernel<<<256, 256>>>(wproj, wt + WT_PROJ_OFF, 384 * 384);
    wround_kernel<<<512, 256>>>(w1,    wt + WT_W1_OFF,   384 * 1536);
    wround_kernel<<<512, 256>>>(w2,    wt + WT_W2_OFF,   1536 * 384);

    // 1) conv + pos bias -> t[m][c]
    {
        int total = BB * CC * NTOK;
        conv_prep_kernel<<<(total + 255) / 256, 256>>>(x, pos_w, pos_b, t);
    }
    // 2) LN1: t -> xn (tf32-rounded)
    ln_kernel<<<MTOT / 8, 256>>>(t, g1, b1, xn);
    // 3) qkv = xn @ wqkv + bqkv
    tgemm_kernel<false, false, false><<<dim3(1152 / 128, MTOT / 128), 256>>>(
        xn, wt + WT_QKV_OFF, bqkv, qkv, MTOT, 1152, 384);
    // 4) attention -> o (tf32-rounded)
    attn_kernel<<<dim3(NTOK / 64, BB * NHEAD), 256>>>(qkv, o);
    // 5) t += o @ wproj + bproj
    tgemm_kernel<true, false, false><<<dim3(384 / 128, MTOT / 128), 256>>>(
        o, wt + WT_PROJ_OFF, bproj, t, MTOT, 384, 384);
    // 6) LN2: t -> xn (tf32-rounded)
    ln_kernel<<<MTOT / 8, 256>>>(t, g2, b2, xn);
    // 7) h = gelu(xn @ w1 + bf1) (tf32-rounded)
    tgemm_kernel<false, true, true><<<dim3(1536 / 128, MTOT / 128), 256>>>(
        xn, wt + WT_W1_OFF, bf1, hbuf, MTOT, 1536, 384);
    // 8) t += h @ w2 + bf2
    tgemm_kernel<true, false, false><<<dim3(384 / 128, MTOT / 128), 256>>>(
        hbuf, wt + WT_W2_OFF, bf2, t, MTOT, 384, 1536);
    // 9) transpose to NCHW
    transpose_kernel<<<dim3(NTOK / 32, CC / 32, BB), dim3(32, 8)>>>(t, out);
}

// round 7
// speedup vs baseline: 1.6332x; 1.0121x over previous
#include <cuda_runtime.h>
#include <cuda_fp16.h>
#include <math.h>
#include <stdint.h>

// Problem constants
#define BB    16
#define CC    384
#define NTOK  1024          // 32*32
#define MTOT  (BB*NTOK)     // 16384 tokens
#define NHEAD 8
#define DH    48

// ---------------- scratch (no allocations allowed) ----------------
__device__ float  g_t  [MTOT*CC];        // fp32 residual stream [m][c]
__device__ float  g_qkv[MTOT*3*CC];      // qkv projection (fp32, attention input)
__device__ __half g_xh [MTOT*CC];        // half activations (LN outputs)
__device__ __half g_oh [MTOT*CC];        // half attention output
__device__ __half g_hh [MTOT*4*CC];      // half mlp hidden
// transposed half weights [N][K]
__device__ __half g_wh [1152*384 + 384*384 + 1536*384 + 384*1536];

#define WH_QKV_OFF  0
#define WH_PROJ_OFF (1152*384)
#define WH_W1_OFF   (WH_PROJ_OFF + 384*384)
#define WH_W2_OFF   (WH_W1_OFF + 1536*384)

// ---------------- helpers ----------------------------------------------
__device__ __forceinline__ uint32_t smem_u32(const void* p) {
    uint32_t a;
    asm("{ .reg .u64 t; cvta.to.shared.u64 t, %1; cvt.u32.u64 %0, t; }" : "=r"(a) : "l"(p));
    return a;
}
__device__ __forceinline__ void cp_async16(uint32_t dst, const void* src) {
    asm volatile("cp.async.ca.shared.global [%0], [%1], 16;" :: "r"(dst), "l"(src));
}
#define CP_COMMIT() asm volatile("cp.async.commit_group;" ::: "memory")
#define CP_WAIT(n)  asm volatile("cp.async.wait_group %0;" :: "n"(n) : "memory")

__device__ __forceinline__ void ldmx4(uint32_t r[4], uint32_t addr) {
    asm volatile("ldmatrix.sync.aligned.m8n8.x4.shared.b16 {%0,%1,%2,%3}, [%4];"
                 : "=r"(r[0]), "=r"(r[1]), "=r"(r[2]), "=r"(r[3]) : "r"(addr));
}

__device__ __forceinline__ void mma_f16(float c[4], const uint32_t a[4],
                                        uint32_t b0, uint32_t b1) {
    asm volatile(
        "mma.sync.aligned.m16n8k16.row.col.f32.f16.f16.f32 "
        "{%0,%1,%2,%3}, {%4,%5,%6,%7}, {%8,%9}, {%0,%1,%2,%3};\n"
        : "+f"(c[0]), "+f"(c[1]), "+f"(c[2]), "+f"(c[3])
        : "r"(a[0]), "r"(a[1]), "r"(a[2]), "r"(a[3]), "r"(b0), "r"(b1));
}

__device__ __forceinline__ float gelu_exact(float x) { return x * normcdff(x); }

// ---------------- kernel 0: transpose + convert weights: W[K][N]->Wt[N][K] h --
__global__ void wtrans_kernel(const float* __restrict__ W, __half* __restrict__ Wt,
                              int K, int N) {
    __shared__ float tile[32][33];
    int k0 = blockIdx.y * 32;
    int n0 = blockIdx.x * 32;
    int tx = threadIdx.x, ty = threadIdx.y;
    #pragma unroll
    for (int i = 0; i < 4; i++)
        tile[ty + 8 * i][tx] = W[(size_t)(k0 + ty + 8 * i) * N + n0 + tx];
    __syncthreads();
    #pragma unroll
    for (int i = 0; i < 4; i++)
        Wt[(size_t)(n0 + ty + 8 * i) * K + k0 + tx] = __float2half(tile[tx][ty + 8 * i]);
}

// ---------------- kernel 1: depthwise conv 3x3 + pos bias + layout change ----
__global__ void conv_prep_kernel(const float* __restrict__ x,
                                 const float* __restrict__ pw,
                                 const float* __restrict__ pb,
                                 float* __restrict__ t) {
    int idx = blockIdx.x * blockDim.x + threadIdx.x;
    if (idx >= BB * CC * NTOK) return;
    int w = idx & 31;
    int h = (idx >> 5) & 31;
    int c = (idx >> 10) % CC;
    int b = idx / (CC * NTOK);
    const float* xp = x + ((size_t)(b * CC + c) << 10);
    const float* k  = pw + c * 9;
    float acc = 0.f;
    #pragma unroll
    for (int dh = -1; dh <= 1; dh++) {
        int hh = h + dh;
        if (hh < 0 || hh > 31) continue;
        #pragma unroll
        for (int dw = -1; dw <= 1; dw++) {
            int ww = w + dw;
            if (ww < 0 || ww > 31) continue;
            acc += xp[hh * 32 + ww] * k[(dh + 1) * 3 + (dw + 1)];
        }
    }
    float v = xp[h * 32 + w] + acc + pb[c];
    t[(size_t)(b * NTOK + h * 32 + w) * CC + c] = v;
}

// ---------------- kernel 2: LayerNorm -> half output ------------------------
__global__ void ln_kernel(const float* __restrict__ in,
                          const float* __restrict__ g,
                          const float* __restrict__ bta,
                          __half* __restrict__ out) {
    int warp = threadIdx.x >> 5;
    int lane = threadIdx.x & 31;
    int row  = blockIdx.x * 8 + warp;
    const float4* ip = (const float4*)(in + (size_t)row * CC);
    float4 v[3];
    #pragma unroll
    for (int i = 0; i < 3; i++) v[i] = ip[lane + 32 * i];
    float s = 0.f;
    #pragma unroll
    for (int i = 0; i < 3; i++) s += v[i].x + v[i].y + v[i].z + v[i].w;
    #pragma unroll
    for (int o = 16; o; o >>= 1) s += __shfl_xor_sync(0xffffffffu, s, o);
    float mu = s * (1.0f / CC);
    float q = 0.f;
    #pragma unroll
    for (int i = 0; i < 3; i++) {
        float a = v[i].x - mu, b2 = v[i].y - mu, c2 = v[i].z - mu, d2 = v[i].w - mu;
        q += a * a + b2 * b2 + c2 * c2 + d2 * d2;
    }
    #pragma unroll
    for (int o = 16; o; o >>= 1) q += __shfl_xor_sync(0xffffffffu, q, o);
    float r = rsqrtf(q * (1.0f / CC) + 1e-5f);
    __half* op = out + (size_t)row * CC;
    const float4* gp = (const float4*)g;
    const float4* bp = (const float4*)bta;
    #pragma unroll
    for (int i = 0; i < 3; i++) {
        float4 gg = gp[lane + 32 * i];
        float4 bb = bp[lane + 32 * i];
        float o0 = (v[i].x - mu) * r * gg.x + bb.x;
        float o1 = (v[i].y - mu) * r * gg.y + bb.y;
        float o2 = (v[i].z - mu) * r * gg.z + bb.z;
        float o3 = (v[i].w - mu) * r * gg.w + bb.w;
        __half2* dst = (__half2*)(op + 4 * lane + 128 * i);
        dst[0] = __floats2half2_rn(o0, o1);
        dst[1] = __floats2half2_rn(o2, o3);
    }
}

// ---------------- kernel 3: fp16 mma.sync GEMM, ldmatrix, double buffered ----
// C[M,N] = epi(A[M,K] @ Bt[N,K]^T + bias). BM=128 BN=128 BK=32, 256 threads,
// 8 warps 4(m)x2(n), warp tile 32x64. A,Bt are half, [row][K] layout.
#define PADK 40   // halves per smem row (32 data + 8 pad); 80B stride -> conflict-free ldmatrix

template<bool RESID, bool GELU, bool OUTH>
__global__ __launch_bounds__(256)
void hgemm_kernel(const __half* __restrict__ A, const __half* __restrict__ Bt,
                  const float* __restrict__ bias, void* __restrict__ Cout,
                  int M, int N, int K) {
    __shared__ __half As[2][128 * PADK];
    __shared__ __half Bs[2][128 * PADK];

    int tid = threadIdx.x;
    int m0 = blockIdx.y * 128;
    int n0 = blockIdx.x * 128;

    int wid  = tid >> 5;
    int lane = tid & 31;
    int wm = (wid >> 1) * 32;
    int wn = (wid & 1) * 64;
    int g  = lane >> 2;
    int t0 = lane & 3;

    // fill: row = tid>>1 (0..127), two 16B chunks at fc, fc+1
    int frow = tid >> 1;
    int fc   = (tid & 1) * 2;
    const __half* ApG = A  + (size_t)(m0 + frow) * K + fc * 8;
    const __half* BpG = Bt + (size_t)(n0 + frow) * K + fc * 8;
    uint32_t sa = smem_u32(&As[0][frow * PADK + fc * 8]);
    uint32_t sb = smem_u32(&Bs[0][frow * PADK + fc * 8]);
    const uint32_t bufBytes = 128 * PADK * 2;

    float acc[2][8][4];
    #pragma unroll
    for (int mt = 0; mt < 2; mt++)
        #pragma unroll
        for (int nt = 0; nt < 8; nt++)
            #pragma unroll
            for (int i = 0; i < 4; i++) acc[mt][nt][i] = 0.f;

    int nkt = K >> 5;

    // prologue
    cp_async16(sa, ApG);
    cp_async16(sa + 16, ApG + 8);
    cp_async16(sb, BpG);
    cp_async16(sb + 16, BpG + 8);
    CP_COMMIT();

    // precomputed fragment addresses (byte offsets into buffer 0)
    uint32_t aOff = (uint32_t)((wm + (lane & 15)) * PADK + ((lane >> 4) & 1) * 8) * 2;
    uint32_t bOff = (uint32_t)((wn + (lane & 7) + ((lane >> 4) & 1) * 8) * PADK +
                               ((lane >> 3) & 1) * 8) * 2;
    uint32_t aBase0 = smem_u32(&As[0][0]);
    uint32_t bBase0 = smem_u32(&Bs[0][0]);

    for (int kt = 0; kt < nkt; kt++) {
        int buf = kt & 1;
        if (kt + 1 < nkt) {
            int nb = 1 - buf;
            const __half* Ap = ApG + (kt + 1) * 32;
            const __half* Bp = BpG + (kt + 1) * 32;
            cp_async16(sa + nb * bufBytes, Ap);
            cp_async16(sa + nb * bufBytes + 16, Ap + 8);
            cp_async16(sb + nb * bufBytes, Bp);
            cp_async16(sb + nb * bufBytes + 16, Bp + 8);
            CP_COMMIT();
            CP_WAIT(1);
        } else {
            CP_WAIT(0);
        }
        __syncthreads();

        uint32_t aB = aBase0 + buf * bufBytes + aOff;
        uint32_t bB = bBase0 + buf * bufBytes + bOff;

        #pragma unroll
        for (int kk = 0; kk < 32; kk += 16) {
            uint32_t a[2][4];
            #pragma unroll
            for (int mt = 0; mt < 2; mt++)
                ldmx4(a[mt], aB + (uint32_t)(mt * 16 * PADK + kk) * 2);
            #pragma unroll
            for (int ntp = 0; ntp < 4; ntp++) {
                uint32_t b[4];
                ldmx4(b, bB + (uint32_t)(ntp * 16 * PADK + kk) * 2);
                mma_f16(acc[0][2 * ntp + 0], a[0], b[0], b[1]);
                mma_f16(acc[1][2 * ntp + 0], a[1], b[0], b[1]);
                mma_f16(acc[0][2 * ntp + 1], a[0], b[2], b[3]);
                mma_f16(acc[1][2 * ntp + 1], a[1], b[2], b[3]);
            }
        }
        __syncthreads();
    }

    // epilogue: thread holds c0,c1 at (row g, cols 2t0..), c2,c3 at row g+8
    #pragma unroll
    for (int mt = 0; mt < 2; mt++) {
        #pragma unroll
        for (int nt = 0; nt < 8; nt++) {
            int row = m0 + wm + mt * 16 + g;
            int col = n0 + wn + nt * 8 + 2 * t0;
            float2 bs = *(const float2*)(bias + col);
            float v0 = acc[mt][nt][0] + bs.x;
            float v1 = acc[mt][nt][1] + bs.y;
            float v2 = acc[mt][nt][2] + bs.x;
            float v3 = acc[mt][nt][3] + bs.y;
            if (GELU) {
                v0 = gelu_exact(v0); v1 = gelu_exact(v1);
                v2 = gelu_exact(v2); v3 = gelu_exact(v3);
            }
            if (OUTH) {
                __half* ch = (__half*)Cout;
                *(__half2*)(ch + (size_t)row * N + col)       = __floats2half2_rn(v0, v1);
                *(__half2*)(ch + (size_t)(row + 8) * N + col) = __floats2half2_rn(v2, v3);
            } else {
                float* cf = (float*)Cout;
                float* cp0 = cf + (size_t)row * N + col;
                float* cp1 = cf + (size_t)(row + 8) * N + col;
                if (RESID) {
                    float2 o0 = *(const float2*)cp0;
                    float2 o1 = *(const float2*)cp1;
                    v0 += o0.x; v1 += o0.y; v2 += o1.x; v3 += o1.y;
                }
                *(float2*)cp0 = make_float2(v0, v1);
                *(float2*)cp1 = make_float2(v2, v3);
            }
        }
    }
}

// ---------------- kernel 4: flash attention (SIMT, fp32; half output) -------
__global__ __launch_bounds__(256)
void attn_kernel(const float* __restrict__ qkv, __half* __restrict__ oh) {
    __shared__ float Qs[64][48];
    __shared__ float Ks[32][48];
    __shared__ float Vs[32][48];
    __shared__ float Ss[64][32];

    int tid = threadIdx.x;
    int bh  = blockIdx.y;
    int b   = bh >> 3, h = bh & 7;
    int q0  = blockIdx.x * 64;
    const float scale = 0.14433756729740643f; // 48^-0.5

    const float* qbase = qkv + (size_t)(b * NTOK + q0) * (3 * CC) + h * DH;
    for (int i = tid; i < 64 * 12; i += 256) {
        int r = i / 12, c4 = i % 12;
        float4 v = *(const float4*)(qbase + (size_t)r * (3 * CC) + c4 * 4);
        v.x *= scale; v.y *= scale; v.z *= scale; v.w *= scale;
        *(float4*)&Qs[r][c4 * 4] = v;
    }

    int rrow = tid >> 2;
    int l4   = tid & 3;
    float m_i = -1e30f, l_i = 0.f;
    float oacc[12];
    #pragma unroll
    for (int d = 0; d < 12; d++) oacc[d] = 0.f;

    int ty = tid >> 4, tx = tid & 15;

    const float* kbase = qkv + (size_t)(b * NTOK) * (3 * CC) + CC + h * DH;
    const float* vbase = kbase + CC;
    __syncthreads();

    for (int kt = 0; kt < 32; kt++) {
        int k0 = kt * 32;
        for (int i = tid; i < 768; i += 256) {
            int which = (i >= 384);
            int j = which ? i - 384 : i;
            int r = j / 12, c4 = j % 12;
            const float* src = (which ? vbase : kbase) + (size_t)(k0 + r) * (3 * CC) + c4 * 4;
            float4 v = *(const float4*)src;
            if (which) *(float4*)&Vs[r][c4 * 4] = v;
            else       *(float4*)&Ks[r][c4 * 4] = v;
        }
        __syncthreads();

        float s[4][2];
        #pragma unroll
        for (int i = 0; i < 4; i++) { s[i][0] = 0.f; s[i][1] = 0.f; }
        #pragma unroll
        for (int kk = 0; kk < 48; kk += 4) {
            float4 qv[4], kv2[2];
            #pragma unroll
            for (int i = 0; i < 4; i++) qv[i] = *(const float4*)&Qs[4 * ty + i][kk];
            #pragma unroll
            for (int j = 0; j < 2; j++) kv2[j] = *(const float4*)&Ks[2 * tx + j][kk];
            #pragma unroll
            for (int i = 0; i < 4; i++)
                #pragma unroll
                for (int j = 0; j < 2; j++)
                    s[i][j] += qv[i].x * kv2[j].x + qv[i].y * kv2[j].y +
                               qv[i].z * kv2[j].z + qv[i].w * kv2[j].w;
        }
        #pragma unroll
        for (int i = 0; i < 4; i++) {
            Ss[4 * ty + i][2 * tx + 0] = s[i][0];
            Ss[4 * ty + i][2 * tx + 1] = s[i][1];
        }
        __syncthreads();

        float4 p0 = *(const float4*)&Ss[rrow][l4 * 8];
        float4 p1 = *(const float4*)&Ss[rrow][l4 * 8 + 4];
        float tm = fmaxf(fmaxf(fmaxf(p0.x, p0.y), fmaxf(p0.z, p0.w)),
                         fmaxf(fmaxf(p1.x, p1.y), fmaxf(p1.z, p1.w)));
        tm = fmaxf(tm, __shfl_xor_sync(0xffffffffu, tm, 1));
        tm = fmaxf(tm, __shfl_xor_sync(0xffffffffu, tm, 2));
        float newm = fmaxf(m_i, tm);
        float alpha = __expf(m_i - newm);
        p0.x = __expf(p0.x - newm); p0.y = __expf(p0.y - newm);
        p0.z = __expf(p0.z - newm); p0.w = __expf(p0.w - newm);
        p1.x = __expf(p1.x - newm); p1.y = __expf(p1.y - newm);
        p1.z = __expf(p1.z - newm); p1.w = __expf(p1.w - newm);
        float rs = p0.x + p0.y + p0.z + p0.w + p1.x + p1.y + p1.z + p1.w;
        rs += __shfl_xor_sync(0xffffffffu, rs, 1);
        rs += __shfl_xor_sync(0xffffffffu, rs, 2);
        l_i = l_i * alpha + rs;
        m_i = newm;
        #pragma unroll
        for (int d = 0; d < 12; d++) oacc[d] *= alpha;
        *(float4*)&Ss[rrow][l4 * 8]     = p0;
        *(float4*)&Ss[rrow][l4 * 8 + 4] = p1;
        __syncwarp();

        #pragma unroll 4
        for (int j = 0; j < 32; j++) {
            float p = Ss[rrow][j];
            float4 v0 = *(const float4*)&Vs[j][l4 * 12];
            float4 v1 = *(const float4*)&Vs[j][l4 * 12 + 4];
            float4 v2 = *(const float4*)&Vs[j][l4 * 12 + 8];
            oacc[0] += p * v0.x; oacc[1] += p * v0.y; oacc[2]  += p * v0.z; oacc[3]  += p * v0.w;
            oacc[4] += p * v1.x; oacc[5] += p * v1.y; oacc[6]  += p * v1.z; oacc[7]  += p * v1.w;
            oacc[8] += p * v2.x; oacc[9] += p * v2.y; oacc[10] += p * v2.z; oacc[11] += p * v2.w;
        }
        __syncthreads();
    }

    float inv = 1.f / l_i;
    __half* op = oh + (size_t)(b * NTOK + q0 + rrow) * CC + h * DH + l4 * 12;
    __half2* oph = (__half2*)op;
    oph[0] = __floats2half2_rn(oacc[0] * inv, oacc[1] * inv);
    oph[1] = __floats2half2_rn(oacc[2] * inv, oacc[3] * inv);
    oph[2] = __floats2half2_rn(oacc[4] * inv, oacc[5] * inv);
    oph[3] = __floats2half2_rn(oacc[6] * inv, oacc[7] * inv);
    oph[4] = __floats2half2_rn(oacc[8] * inv, oacc[9] * inv);
    oph[5] = __floats2half2_rn(oacc[10] * inv, oacc[11] * inv);
}

// ---------------- kernel 5: final transpose to NCHW -------------------------
__global__ void transpose_kernel(const float* __restrict__ t, float* __restrict__ out) {
    __shared__ float tile[32][33];
    int b  = blockIdx.z;
    int n0 = blockIdx.x * 32;
    int c0 = blockIdx.y * 32;
    int tx = threadIdx.x, ty = threadIdx.y;
    #pragma unroll
    for (int i = 0; i < 4; i++)
        tile[ty + 8 * i][tx] = t[(size_t)(b * NTOK + n0 + ty + 8 * i) * CC + c0 + tx];
    __syncthreads();
    #pragma unroll
    for (int i = 0; i < 4; i++)
        out[(size_t)(b * CC + c0 + ty + 8 * i) * NTOK + n0 + tx] = tile[tx][ty + 8 * i];
}

// ---------------- launch ----------------------------------------------------
extern "C" void kernel_launch(void* const* d_in, const int* in_sizes, int n_in,
                              void* d_out, int out_size) {
    const float* x     = (const float*)d_in[0];
    const float* pos_w = (const float*)d_in[1];
    const float* pos_b = (const float*)d_in[2];
    const float* g1    = (const float*)d_in[3];
    const float* b1    = (const float*)d_in[4];
    const float* wqkv  = (const float*)d_in[5];
    const float* bqkv  = (const float*)d_in[6];
    const float* wproj = (const float*)d_in[7];
    const float* bproj = (const float*)d_in[8];
    const float* g2    = (const float*)d_in[9];
    const float* b2    = (const float*)d_in[10];
    const float* w1    = (const float*)d_in[11];
    const float* bf1   = (const float*)d_in[12];
    const float* w2    = (const float*)d_in[13];
    const float* bf2   = (const float*)d_in[14];
    float* out = (float*)d_out;

    float *t, *qkv;
    __half *xh, *ohh, *hh, *wh;
    cudaGetSymbolAddress((void**)&t,   g_t);
    cudaGetSymbolAddress((void**)&qkv, g_qkv);
    cudaGetSymbolAddress((void**)&xh,  g_xh);
    cudaGetSymbolAddress((void**)&ohh, g_oh);
    cudaGetSymbolAddress((void**)&hh,  g_hh);
    cudaGetSymbolAddress((void**)&wh,  g_wh);

    // 0) transpose + convert weights to half [N][K]
    wtrans_kernel<<<dim3(1152 / 32, 384 / 32),  dim3(32, 8)>>>(wqkv,  wh + WH_QKV_OFF,  384, 1152);
    wtrans_kernel<<<dim3(384 / 32,  384 / 32),  dim3(32, 8)>>>(wproj, wh + WH_PROJ_OFF, 384, 384);
    wtrans_kernel<<<dim3(1536 / 32, 384 / 32),  dim3(32, 8)>>>(w1,    wh + WH_W1_OFF,   384, 1536);
    wtrans_kernel<<<dim3(384 / 32,  1536 / 32), dim3(32, 8)>>>(w2,    wh + WH_W2_OFF,   1536, 384);

    // 1) conv + pos bias -> t[m][c]
    {
        int total = BB * CC * NTOK;
        conv_prep_kernel<<<(total + 255) / 256, 256>>>(x, pos_w, pos_b, t);
    }
    // 2) LN1: t -> xh (half)
    ln_kernel<<<MTOT / 8, 256>>>(t, g1, b1, xh);
    // 3) qkv = xh @ wqkv + bqkv (fp32 out)
    hgemm_kernel<false, false, false><<<dim3(1152 / 128, MTOT / 128), 256>>>(
        xh, wh + WH_QKV_OFF, bqkv, qkv, MTOT, 1152, 384);
    // 4) attention -> oh (half)
    attn_kernel<<<dim3(NTOK / 64, BB * NHEAD), 256>>>(qkv, ohh);
    // 5) t += oh @ wproj + bproj (fp32 resid)
    hgemm_kernel<true, false, false><<<dim3(384 / 128, MTOT / 128), 256>>>(
        ohh, wh + WH_PROJ_OFF, bproj, t, MTOT, 384, 384);
    // 6) LN2: t -> xh (half)
    ln_kernel<<<MTOT / 8, 256>>>(t, g2, b2, xh);
    // 7) hh = gelu(xh @ w1 + bf1) (half out)
    hgemm_kernel<false, true, true><<<dim3(1536 / 128, MTOT / 128), 256>>>(
        xh, wh + WH_W1_OFF, bf1, hh, MTOT, 1536, 384);
    // 8) t += hh @ w2 + bf2 (fp32 resid)
    hgemm_kernel<true, false, false><<<dim3(384 / 128, MTOT / 128), 256>>>(
        hh, wh + WH_W2_OFF, bf2, t, MTOT, 384, 1536);
    // 9) transpose to NCHW
    transpose_kernel<<<dim3(NTOK / 32, CC / 32, BB), dim3(32, 8)>>>(t, out);
}

// round 9
// speedup vs baseline: 8.9918x; 5.5057x over previous
#include <cuda_runtime.h>
#include <cuda_fp16.h>
#include <math.h>
#include <stdint.h>

// Problem constants
#define BB    16
#define CC    384
#define NTOK  1024          // 32*32
#define MTOT  (BB*NTOK)     // 16384 tokens
#define NHEAD 8
#define DH    48

// ---------------- scratch (no allocations allowed) ----------------
__device__ float  g_t   [MTOT*CC];       // fp32 residual stream [m][c]
__device__ __half g_qkvh[MTOT*3*CC];     // half qkv [m][1152]
__device__ __half g_xh  [MTOT*CC];       // half activations (LN outputs)
__device__ __half g_oh  [MTOT*CC];       // half attention output
__device__ __half g_hh  [MTOT*4*CC];     // half mlp hidden
// transposed half weights [N][K]
__device__ __half g_wh [1152*384 + 384*384 + 1536*384 + 384*1536];

#define WH_QKV_OFF  0
#define WH_PROJ_OFF (1152*384)
#define WH_W1_OFF   (WH_PROJ_OFF + 384*384)
#define WH_W2_OFF   (WH_W1_OFF + 1536*384)

// ---------------- helpers ----------------------------------------------
__device__ __forceinline__ uint32_t smem_u32(const void* p) {
    uint32_t a;
    asm("{ .reg .u64 t; cvta.to.shared.u64 t, %1; cvt.u32.u64 %0, t; }" : "=r"(a) : "l"(p));
    return a;
}
__device__ __forceinline__ void cp_async16(uint32_t dst, const void* src) {
    asm volatile("cp.async.ca.shared.global [%0], [%1], 16;" :: "r"(dst), "l"(src));
}
#define CP_COMMIT() asm volatile("cp.async.commit_group;" ::: "memory")
#define CP_WAIT(n)  asm volatile("cp.async.wait_group %0;" :: "n"(n) : "memory")

__device__ __forceinline__ void ldmx4(uint32_t r[4], uint32_t addr) {
    asm volatile("ldmatrix.sync.aligned.m8n8.x4.shared.b16 {%0,%1,%2,%3}, [%4];"
                 : "=r"(r[0]), "=r"(r[1]), "=r"(r[2]), "=r"(r[3]) : "r"(addr));
}
__device__ __forceinline__ void ldmx4t(uint32_t r[4], uint32_t addr) {
    asm volatile("ldmatrix.sync.aligned.m8n8.x4.trans.shared.b16 {%0,%1,%2,%3}, [%4];"
                 : "=r"(r[0]), "=r"(r[1]), "=r"(r[2]), "=r"(r[3]) : "r"(addr));
}

__device__ __forceinline__ void mma_f16(float c[4], const uint32_t a[4],
                                        uint32_t b0, uint32_t b1) {
    asm volatile(
        "mma.sync.aligned.m16n8k16.row.col.f32.f16.f16.f32 "
        "{%0,%1,%2,%3}, {%4,%5,%6,%7}, {%8,%9}, {%0,%1,%2,%3};\n"
        : "+f"(c[0]), "+f"(c[1]), "+f"(c[2]), "+f"(c[3])
        : "r"(a[0]), "r"(a[1]), "r"(a[2]), "r"(a[3]), "r"(b0), "r"(b1));
}

__device__ __forceinline__ uint32_t pack_h2(float lo, float hi) {
    __half2 v = __floats2half2_rn(lo, hi);
    return *reinterpret_cast<uint32_t*>(&v);
}

__device__ __forceinline__ float gelu_exact(float x) { return x * normcdff(x); }

// ---------------- kernel 0: transpose + convert weights: W[K][N]->Wt[N][K] h --
__global__ void wtrans_kernel(const float* __restrict__ W, __half* __restrict__ Wt,
                              int K, int N) {
    __shared__ float tile[32][33];
    int k0 = blockIdx.y * 32;
    int n0 = blockIdx.x * 32;
    int tx = threadIdx.x, ty = threadIdx.y;
    #pragma unroll
    for (int i = 0; i < 4; i++)
        tile[ty + 8 * i][tx] = W[(size_t)(k0 + ty + 8 * i) * N + n0 + tx];
    __syncthreads();
    #pragma unroll
    for (int i = 0; i < 4; i++)
        Wt[(size_t)(n0 + ty + 8 * i) * K + k0 + tx] = __float2half(tile[tx][ty + 8 * i]);
}

// ---------------- kernel 1: depthwise conv 3x3 + pos bias + layout change ----
__global__ void conv_prep_kernel(const float* __restrict__ x,
                                 const float* __restrict__ pw,
                                 const float* __restrict__ pb,
                                 float* __restrict__ t) {
    int idx = blockIdx.x * blockDim.x + threadIdx.x;
    if (idx >= BB * CC * NTOK) return;
    int w = idx & 31;
    int h = (idx >> 5) & 31;
    int c = (idx >> 10) % CC;
    int b = idx / (CC * NTOK);
    const float* xp = x + ((size_t)(b * CC + c) << 10);
    const float* k  = pw + c * 9;
    float acc = 0.f;
    #pragma unroll
    for (int dh = -1; dh <= 1; dh++) {
        int hh = h + dh;
        if (hh < 0 || hh > 31) continue;
        #pragma unroll
        for (int dw = -1; dw <= 1; dw++) {
            int ww = w + dw;
            if (ww < 0 || ww > 31) continue;
            acc += xp[hh * 32 + ww] * k[(dh + 1) * 3 + (dw + 1)];
        }
    }
    float v = xp[h * 32 + w] + acc + pb[c];
    t[(size_t)(b * NTOK + h * 32 + w) * CC + c] = v;
}

// ---------------- kernel 2: LayerNorm -> half output ------------------------
__global__ void ln_kernel(const float* __restrict__ in,
                          const float* __restrict__ g,
                          const float* __restrict__ bta,
                          __half* __restrict__ out) {
    int warp = threadIdx.x >> 5;
    int lane = threadIdx.x & 31;
    int row  = blockIdx.x * 8 + warp;
    const float4* ip = (const float4*)(in + (size_t)row * CC);
    float4 v[3];
    #pragma unroll
    for (int i = 0; i < 3; i++) v[i] = ip[lane + 32 * i];
    float s = 0.f;
    #pragma unroll
    for (int i = 0; i < 3; i++) s += v[i].x + v[i].y + v[i].z + v[i].w;
    #pragma unroll
    for (int o = 16; o; o >>= 1) s += __shfl_xor_sync(0xffffffffu, s, o);
    float mu = s * (1.0f / CC);
    float q = 0.f;
    #pragma unroll
    for (int i = 0; i < 3; i++) {
        float a = v[i].x - mu, b2 = v[i].y - mu, c2 = v[i].z - mu, d2 = v[i].w - mu;
        q += a * a + b2 * b2 + c2 * c2 + d2 * d2;
    }
    #pragma unroll
    for (int o = 16; o; o >>= 1) q += __shfl_xor_sync(0xffffffffu, q, o);
    float r = rsqrtf(q * (1.0f / CC) + 1e-5f);
    __half* op = out + (size_t)row * CC;
    const float4* gp = (const float4*)g;
    const float4* bp = (const float4*)bta;
    #pragma unroll
    for (int i = 0; i < 3; i++) {
        float4 gg = gp[lane + 32 * i];
        float4 bb = bp[lane + 32 * i];
        float o0 = (v[i].x - mu) * r * gg.x + bb.x;
        float o1 = (v[i].y - mu) * r * gg.y + bb.y;
        float o2 = (v[i].z - mu) * r * gg.z + bb.z;
        float o3 = (v[i].w - mu) * r * gg.w + bb.w;
        __half2* dst = (__half2*)(op + 4 * lane + 128 * i);
        dst[0] = __floats2half2_rn(o0, o1);
        dst[1] = __floats2half2_rn(o2, o3);
    }
}

// ---------------- kernel 3: fp16 mma.sync GEMM, ldmatrix, double buffered ----
#define PADK 40   // halves per smem row; 80B stride -> conflict-free ldmatrix

template<bool RESID, bool GELU, bool OUTH>
__global__ __launch_bounds__(256)
void hgemm_kernel(const __half* __restrict__ A, const __half* __restrict__ Bt,
                  const float* __restrict__ bias, void* __restrict__ Cout,
                  int M, int N, int K) {
    __shared__ __half As[2][128 * PADK];
    __shared__ __half Bs[2][128 * PADK];

    int tid = threadIdx.x;
    int m0 = blockIdx.y * 128;
    int n0 = blockIdx.x * 128;

    int wid  = tid >> 5;
    int lane = tid & 31;
    int wm = (wid >> 1) * 32;
    int wn = (wid & 1) * 64;
    int g  = lane >> 2;
    int t0 = lane & 3;

    int frow = tid >> 1;
    int fc   = (tid & 1) * 2;
    const __half* ApG = A  + (size_t)(m0 + frow) * K + fc * 8;
    const __half* BpG = Bt + (size_t)(n0 + frow) * K + fc * 8;
    uint32_t sa = smem_u32(&As[0][frow * PADK + fc * 8]);
    uint32_t sb = smem_u32(&Bs[0][frow * PADK + fc * 8]);
    const uint32_t bufBytes = 128 * PADK * 2;

    float acc[2][8][4];
    #pragma unroll
    for (int mt = 0; mt < 2; mt++)
        #pragma unroll
        for (int nt = 0; nt < 8; nt++)
            #pragma unroll
            for (int i = 0; i < 4; i++) acc[mt][nt][i] = 0.f;

    int nkt = K >> 5;

    cp_async16(sa, ApG);
    cp_async16(sa + 16, ApG + 8);
    cp_async16(sb, BpG);
    cp_async16(sb + 16, BpG + 8);
    CP_COMMIT();

    uint32_t aOff = (uint32_t)((wm + (lane & 15)) * PADK + ((lane >> 4) & 1) * 8) * 2;
    uint32_t bOff = (uint32_t)((wn + (lane & 7) + ((lane >> 4) & 1) * 8) * PADK +
                               ((lane >> 3) & 1) * 8) * 2;
    uint32_t aBase0 = smem_u32(&As[0][0]);
    uint32_t bBase0 = smem_u32(&Bs[0][0]);

    for (int kt = 0; kt < nkt; kt++) {
        int buf = kt & 1;
        if (kt + 1 < nkt) {
            int nb = 1 - buf;
            const __half* Ap = ApG + (kt + 1) * 32;
            const __half* Bp = BpG + (kt + 1) * 32;
            cp_async16(sa + nb * bufBytes, Ap);
            cp_async16(sa + nb * bufBytes + 16, Ap + 8);
            cp_async16(sb + nb * bufBytes, Bp);
            cp_async16(sb + nb * bufBytes + 16, Bp + 8);
            CP_COMMIT();
            CP_WAIT(1);
        } else {
            CP_WAIT(0);
        }
        __syncthreads();

        uint32_t aB = aBase0 + buf * bufBytes + aOff;
        uint32_t bB = bBase0 + buf * bufBytes + bOff;

        #pragma unroll
        for (int kk = 0; kk < 32; kk += 16) {
            uint32_t a[2][4];
            #pragma unroll
            for (int mt = 0; mt < 2; mt++)
                ldmx4(a[mt], aB + (uint32_t)(mt * 16 * PADK + kk) * 2);
            #pragma unroll
            for (int ntp = 0; ntp < 4; ntp++) {
                uint32_t b[4];
                ldmx4(b, bB + (uint32_t)(ntp * 16 * PADK + kk) * 2);
                mma_f16(acc[0][2 * ntp + 0], a[0], b[0], b[1]);
                mma_f16(acc[1][2 * ntp + 0], a[1], b[0], b[1]);
                mma_f16(acc[0][2 * ntp + 1], a[0], b[2], b[3]);
                mma_f16(acc[1][2 * ntp + 1], a[1], b[2], b[3]);
            }
        }
        __syncthreads();
    }

    #pragma unroll
    for (int mt = 0; mt < 2; mt++) {
        #pragma unroll
        for (int nt = 0; nt < 8; nt++) {
            int row = m0 + wm + mt * 16 + g;
            int col = n0 + wn + nt * 8 + 2 * t0;
            float2 bs = *(const float2*)(bias + col);
            float v0 = acc[mt][nt][0] + bs.x;
            float v1 = acc[mt][nt][1] + bs.y;
            float v2 = acc[mt][nt][2] + bs.x;
            float v3 = acc[mt][nt][3] + bs.y;
            if (GELU) {
                v0 = gelu_exact(v0); v1 = gelu_exact(v1);
                v2 = gelu_exact(v2); v3 = gelu_exact(v3);
            }
            if (OUTH) {
                __half* ch = (__half*)Cout;
                *(__half2*)(ch + (size_t)row * N + col)       = __floats2half2_rn(v0, v1);
                *(__half2*)(ch + (size_t)(row + 8) * N + col) = __floats2half2_rn(v2, v3);
            } else {
                float* cf = (float*)Cout;
                float* cp0 = cf + (size_t)row * N + col;
                float* cp1 = cf + (size_t)(row + 8) * N + col;
                if (RESID) {
                    float2 o0 = *(const float2*)cp0;
                    float2 o1 = *(const float2*)cp1;
                    v0 += o0.x; v1 += o0.y; v2 += o1.x; v3 += o1.y;
                }
                *(float2*)cp0 = make_float2(v0, v1);
                *(float2*)cp1 = make_float2(v2, v3);
            }
        }
    }
}

// ---------------- kernel 4: fp16 mma flash attention -------------------------
// 128 threads (4 warps), 64 q-rows/CTA, kv tiles of 64. qkv half [m][1152].
#define PADA 56   // 48 + 8 halves; 112B row stride -> conflict-free ldmatrix

__global__ __launch_bounds__(128)
void attn_mma_kernel(const __half* __restrict__ qkv, __half* __restrict__ oh) {
    __shared__ __half Qs[64 * PADA];
    __shared__ __half Ks[64 * PADA];
    __shared__ __half Vs[64 * PADA];

    int tid  = threadIdx.x;
    int wid  = tid >> 5;
    int lane = tid & 31;
    int g    = lane >> 2;
    int t0   = lane & 3;
    int bh   = blockIdx.y;
    int b    = bh >> 3, h = bh & 7;
    int q0   = blockIdx.x * 64;
    const float scale = 0.14433756729740643f; // 48^-0.5

    const __half* qbase = qkv + (size_t)(b * NTOK) * (3 * CC) + h * DH;

    // load Q tile (64 rows x 48 halves) via cp.async: 384 16B chunks, 3/thread
    {
        uint32_t qs = smem_u32(Qs);
        #pragma unroll
        for (int i = 0; i < 3; i++) {
            int chunk = tid * 3 + i;
            int r = chunk / 6, c = chunk % 6;
            cp_async16(qs + (uint32_t)(r * PADA + c * 8) * 2,
                       qbase + (size_t)(q0 + r) * (3 * CC) + c * 8);
        }
        CP_COMMIT();
    }

    // per-thread state
    float m_r[2] = {-1e30f, -1e30f};
    float l_r[2] = {0.f, 0.f};
    float accO[6][4];
    #pragma unroll
    for (int nt = 0; nt < 6; nt++)
        #pragma unroll
        for (int i = 0; i < 4; i++) accO[nt][i] = 0.f;

    // fragment addresses
    uint32_t qaOff = (uint32_t)((wid * 16 + (lane & 15)) * PADA + ((lane >> 4) & 1) * 8) * 2;
    uint32_t kbOff = (uint32_t)(((lane & 7) + ((lane >> 4) & 1) * 8) * PADA +
                                ((lane >> 3) & 1) * 8) * 2;
    uint32_t vtOff = (uint32_t)(((lane & 7) + ((lane >> 3) & 1) * 8) * PADA +
                                ((lane >> 4) & 1) * 8) * 2;
    uint32_t qB = smem_u32(Qs) + qaOff;
    uint32_t kB = smem_u32(Ks) + kbOff;
    uint32_t vB = smem_u32(Vs) + vtOff;

    CP_WAIT(0);
    __syncthreads();

    // Q fragments held in registers for the whole kernel (3 k-steps of 16)
    uint32_t qf[3][4];
    #pragma unroll
    for (int ks = 0; ks < 3; ks++) ldmx4(qf[ks], qB + (uint32_t)(ks * 16) * 2);

    const __half* kbase = qkv + (size_t)(b * NTOK) * (3 * CC) + CC + h * DH;
    const __half* vbase = kbase + CC;

    for (int kt = 0; kt < 16; kt++) {
        int k0 = kt * 64;
        // load K,V tiles: 2 x 384 chunks, 3+3 per thread
        {
            uint32_t ks = smem_u32(Ks), vs = smem_u32(Vs);
            #pragma unroll
            for (int i = 0; i < 3; i++) {
                int chunk = tid * 3 + i;
                int r = chunk / 6, c = chunk % 6;
                cp_async16(ks + (uint32_t)(r * PADA + c * 8) * 2,
                           kbase + (size_t)(k0 + r) * (3 * CC) + c * 8);
                cp_async16(vs + (uint32_t)(r * PADA + c * 8) * 2,
                           vbase + (size_t)(k0 + r) * (3 * CC) + c * 8);
            }
            CP_COMMIT();
            CP_WAIT(0);
        }
        __syncthreads();

        // S = Q @ K^T : 8 n-tiles of 8 kv each
        float S[8][4];
        #pragma unroll
        for (int nt = 0; nt < 8; nt++)
            #pragma unroll
            for (int i = 0; i < 4; i++) S[nt][i] = 0.f;
        #pragma unroll
        for (int nt16 = 0; nt16 < 4; nt16++) {
            #pragma unroll
            for (int ks = 0; ks < 3; ks++) {
                uint32_t kf[4];
                ldmx4(kf, kB + (uint32_t)(nt16 * 16 * PADA + ks * 16) * 2);
                mma_f16(S[2 * nt16 + 0], qf[ks], kf[0], kf[1]);
                mma_f16(S[2 * nt16 + 1], qf[ks], kf[2], kf[3]);
            }
        }

        // online softmax on fragments (rows g and g+8)
        float tmax0 = -1e30f, tmax1 = -1e30f;
        #pragma unroll
        for (int nt = 0; nt < 8; nt++) {
            #pragma unroll
            for (int i = 0; i < 4; i++) S[nt][i] *= scale;
            tmax0 = fmaxf(tmax0, fmaxf(S[nt][0], S[nt][1]));
            tmax1 = fmaxf(tmax1, fmaxf(S[nt][2], S[nt][3]));
        }
        tmax0 = fmaxf(tmax0, __shfl_xor_sync(0xffffffffu, tmax0, 1));
        tmax0 = fmaxf(tmax0, __shfl_xor_sync(0xffffffffu, tmax0, 2));
        tmax1 = fmaxf(tmax1, __shfl_xor_sync(0xffffffffu, tmax1, 1));
        tmax1 = fmaxf(tmax1, __shfl_xor_sync(0xffffffffu, tmax1, 2));
        float nm0 = fmaxf(m_r[0], tmax0);
        float nm1 = fmaxf(m_r[1], tmax1);
        float al0 = __expf(m_r[0] - nm0);
        float al1 = __expf(m_r[1] - nm1);
        m_r[0] = nm0; m_r[1] = nm1;
        float rs0 = 0.f, rs1 = 0.f;
        #pragma unroll
        for (int nt = 0; nt < 8; nt++) {
            S[nt][0] = __expf(S[nt][0] - nm0);
            S[nt][1] = __expf(S[nt][1] - nm0);
            S[nt][2] = __expf(S[nt][2] - nm1);
            S[nt][3] = __expf(S[nt][3] - nm1);
            rs0 += S[nt][0] + S[nt][1];
            rs1 += S[nt][2] + S[nt][3];
        }
        rs0 += __shfl_xor_sync(0xffffffffu, rs0, 1);
        rs0 += __shfl_xor_sync(0xffffffffu, rs0, 2);
        rs1 += __shfl_xor_sync(0xffffffffu, rs1, 1);
        rs1 += __shfl_xor_sync(0xffffffffu, rs1, 2);
        l_r[0] = l_r[0] * al0 + rs0;
        l_r[1] = l_r[1] * al1 + rs1;
        #pragma unroll
        for (int nt = 0; nt < 6; nt++) {
            accO[nt][0] *= al0; accO[nt][1] *= al0;
            accO[nt][2] *= al1; accO[nt][3] *= al1;
        }

        // P (half) A-fragments from S; O += P @ V
        #pragma unroll
        for (int kb = 0; kb < 4; kb++) {
            uint32_t pa[4];
            pa[0] = pack_h2(S[2 * kb][0],     S[2 * kb][1]);
            pa[1] = pack_h2(S[2 * kb][2],     S[2 * kb][3]);
            pa[2] = pack_h2(S[2 * kb + 1][0], S[2 * kb + 1][1]);
            pa[3] = pack_h2(S[2 * kb + 1][2], S[2 * kb + 1][3]);
            #pragma unroll
            for (int n16 = 0; n16 < 3; n16++) {
                uint32_t vf[4];
                ldmx4t(vf, vB + (uint32_t)(kb * 16 * PADA + n16 * 16) * 2);
                mma_f16(accO[2 * n16 + 0], pa, vf[0], vf[1]);
                mma_f16(accO[2 * n16 + 1], pa, vf[2], vf[3]);
            }
        }
        __syncthreads();
    }

    // write O (half) with 1/l normalization
    float inv0 = 1.f / l_r[0];
    float inv1 = 1.f / l_r[1];
    int row0 = b * NTOK + q0 + wid * 16 + g;
    __half* outp = oh + (size_t)row0 * CC + h * DH + 2 * t0;
    #pragma unroll
    for (int nt = 0; nt < 6; nt++) {
        *(__half2*)(outp + nt * 8) =
            __floats2half2_rn(accO[nt][0] * inv0, accO[nt][1] * inv0);
        *(__half2*)(outp + (size_t)8 * CC + nt * 8) =
            __floats2half2_rn(accO[nt][2] * inv1, accO[nt][3] * inv1);
    }
}

// ---------------- kernel 5: final transpose to NCHW -------------------------
__global__ void transpose_kernel(const float* __restrict__ t, float* __restrict__ out) {
    __shared__ float tile[32][33];
    int b  = blockIdx.z;
    int n0 = blockIdx.x * 32;
    int c0 = blockIdx.y * 32;
    int tx = threadIdx.x, ty = threadIdx.y;
    #pragma unroll
    for (int i = 0; i < 4; i++)
        tile[ty + 8 * i][tx] = t[(size_t)(b * NTOK + n0 + ty + 8 * i) * CC + c0 + tx];
    __syncthreads();
    #pragma unroll
    for (int i = 0; i < 4; i++)
        out[(size_t)(b * CC + c0 + ty + 8 * i) * NTOK + n0 + tx] = tile[tx][ty + 8 * i];
}

// ---------------- launch ----------------------------------------------------
extern "C" void kernel_launch(void* const* d_in, const int* in_sizes, int n_in,
                              void* d_out, int out_size) {
    const float* x     = (const float*)d_in[0];
    const float* pos_w = (const float*)d_in[1];
    const float* pos_b = (const float*)d_in[2];
    const float* g1    = (const float*)d_in[3];
    const float* b1    = (const float*)d_in[4];
    const float* wqkv  = (const float*)d_in[5];
    const float* bqkv  = (const float*)d_in[6];
    const float* wproj = (const float*)d_in[7];
    const float* bproj = (const float*)d_in[8];
    const float* g2    = (const float*)d_in[9];
    const float* b2    = (const float*)d_in[10];
    const float* w1    = (const float*)d_in[11];
    const float* bf1   = (const float*)d_in[12];
    const float* w2    = (const float*)d_in[13];
    const float* bf2   = (const float*)d_in[14];
    float* out = (float*)d_out;

    float *t;
    __half *qkvh, *xh, *ohh, *hh, *wh;
    cudaGetSymbolAddress((void**)&t,    g_t);
    cudaGetSymbolAddress((void**)&qkvh, g_qkvh);
    cudaGetSymbolAddress((void**)&xh,   g_xh);
    cudaGetSymbolAddress((void**)&ohh,  g_oh);
    cudaGetSymbolAddress((void**)&hh,   g_hh);
    cudaGetSymbolAddress((void**)&wh,   g_wh);

    // 0) transpose + convert weights to half [N][K]
    wtrans_kernel<<<dim3(1152 / 32, 384 / 32),  dim3(32, 8)>>>(wqkv,  wh + WH_QKV_OFF,  384, 1152);
    wtrans_kernel<<<dim3(384 / 32,  384 / 32),  dim3(32, 8)>>>(wproj, wh + WH_PROJ_OFF, 384, 384);
    wtrans_kernel<<<dim3(1536 / 32, 384 / 32),  dim3(32, 8)>>>(w1,    wh + WH_W1_OFF,   384, 1536);
    wtrans_kernel<<<dim3(384 / 32,  1536 / 32), dim3(32, 8)>>>(w2,    wh + WH_W2_OFF,   1536, 384);

    // 1) conv + pos bias -> t[m][c]
    {
        int total = BB * CC * NTOK;
        conv_prep_kernel<<<(total + 255) / 256, 256>>>(x, pos_w, pos_b, t);
    }
    // 2) LN1: t -> xh (half)
    ln_kernel<<<MTOT / 8, 256>>>(t, g1, b1, xh);
    // 3) qkv = xh @ wqkv + bqkv (half out)
    hgemm_kernel<false, false, true><<<dim3(1152 / 128, MTOT / 128), 256>>>(
        xh, wh + WH_QKV_OFF, bqkv, qkvh, MTOT, 1152, 384);
    // 4) attention (fp16 mma flash) -> oh (half)
    attn_mma_kernel<<<dim3(NTOK / 64, BB * NHEAD), 128>>>(qkvh, ohh);
    // 5) t += oh @ wproj + bproj (fp32 resid)
    hgemm_kernel<true, false, false><<<dim3(384 / 128, MTOT / 128), 256>>>(
        ohh, wh + WH_PROJ_OFF, bproj, t, MTOT, 384, 384);
    // 6) LN2: t -> xh (half)
    ln_kernel<<<MTOT / 8, 256>>>(t, g2, b2, xh);
    // 7) hh = gelu(xh @ w1 + bf1) (half out)
    hgemm_kernel<false, true, true><<<dim3(1536 / 128, MTOT / 128), 256>>>(
        xh, wh + WH_W1_OFF, bf1, hh, MTOT, 1536, 384);
    // 8) t += hh @ w2 + bf2 (fp32 resid)
    hgemm_kernel<true, false, false><<<dim3(384 / 128, MTOT / 128), 256>>>(
        hh, wh + WH_W2_OFF, bf2, t, MTOT, 384, 1536);
    // 9) transpose to NCHW
    transpose_kernel<<<dim3(NTOK / 32, CC / 32, BB), dim3(32, 8)>>>(t, out);
}

// round 12
// speedup vs baseline: 9.5545x; 1.0626x over previous
#include <cuda_runtime.h>
#include <cuda_fp16.h>
#include <math.h>
#include <stdint.h>

// Problem constants
#define BB    16
#define CC    384
#define NTOK  1024          // 32*32
#define MTOT  (BB*NTOK)     // 16384 tokens
#define NHEAD 8
#define DH    48

// ---------------- scratch (no allocations allowed) ----------------
__device__ float  g_t   [MTOT*CC];       // fp32 residual stream [m][c]
__device__ __half g_qkvh[MTOT*3*CC];     // half qkv [m][1152]
__device__ __half g_xh  [MTOT*CC];       // half activations (LN outputs)
__device__ __half g_oh  [MTOT*CC];       // half attention output
__device__ __half g_hh  [MTOT*4*CC];     // half mlp hidden
// transposed half weights [N][K]
__device__ __half g_wh [1152*384 + 384*384 + 1536*384 + 384*1536];

#define WH_QKV_OFF  0
#define WH_PROJ_OFF (1152*384)
#define WH_W1_OFF   (WH_PROJ_OFF + 384*384)
#define WH_W2_OFF   (WH_W1_OFF + 1536*384)

// ---------------- helpers ----------------------------------------------
__device__ __forceinline__ uint32_t smem_u32(const void* p) {
    uint32_t a;
    asm("{ .reg .u64 t; cvta.to.shared.u64 t, %1; cvt.u32.u64 %0, t; }" : "=r"(a) : "l"(p));
    return a;
}
__device__ __forceinline__ void cp_async16(uint32_t dst, const void* src) {
    asm volatile("cp.async.ca.shared.global [%0], [%1], 16;" :: "r"(dst), "l"(src));
}
#define CP_COMMIT() asm volatile("cp.async.commit_group;" ::: "memory")
#define CP_WAIT(n)  asm volatile("cp.async.wait_group %0;" :: "n"(n) : "memory")

__device__ __forceinline__ void ldmx4(uint32_t r[4], uint32_t addr) {
    asm volatile("ldmatrix.sync.aligned.m8n8.x4.shared.b16 {%0,%1,%2,%3}, [%4];"
                 : "=r"(r[0]), "=r"(r[1]), "=r"(r[2]), "=r"(r[3]) : "r"(addr));
}
__device__ __forceinline__ void ldmx4t(uint32_t r[4], uint32_t addr) {
    asm volatile("ldmatrix.sync.aligned.m8n8.x4.trans.shared.b16 {%0,%1,%2,%3}, [%4];"
                 : "=r"(r[0]), "=r"(r[1]), "=r"(r[2]), "=r"(r[3]) : "r"(addr));
}

__device__ __forceinline__ void mma_f16(float c[4], const uint32_t a[4],
                                        uint32_t b0, uint32_t b1) {
    asm volatile(
        "mma.sync.aligned.m16n8k16.row.col.f32.f16.f16.f32 "
        "{%0,%1,%2,%3}, {%4,%5,%6,%7}, {%8,%9}, {%0,%1,%2,%3};\n"
        : "+f"(c[0]), "+f"(c[1]), "+f"(c[2]), "+f"(c[3])
        : "r"(a[0]), "r"(a[1]), "r"(a[2]), "r"(a[3]), "r"(b0), "r"(b1));
}

__device__ __forceinline__ uint32_t pack_h2(float lo, float hi) {
    __half2 v = __floats2half2_rn(lo, hi);
    return *reinterpret_cast<uint32_t*>(&v);
}

__device__ __forceinline__ float gelu_exact(float x) { return x * normcdff(x); }

// ---------------- kernel 0: ALL weight transposes in one launch --------------
// W[K][N] -> Wt[N][K] half. Dispatch by block index over 4 segments.
__global__ void wtrans_all_kernel(const float* __restrict__ wqkv,
                                  const float* __restrict__ wproj,
                                  const float* __restrict__ w1,
                                  const float* __restrict__ w2,
                                  __half* __restrict__ wh) {
    __shared__ float tile[32][33];
    int blk = blockIdx.x;
    const float* W; __half* Wt; int K, N, nbx;
    if (blk < 432)       { W = wqkv;  Wt = wh + WH_QKV_OFF;  K = 384;  N = 1152; nbx = 36; }
    else if (blk < 576)  { blk -= 432;  W = wproj; Wt = wh + WH_PROJ_OFF; K = 384;  N = 384;  nbx = 12; }
    else if (blk < 1152) { blk -= 576;  W = w1;    Wt = wh + WH_W1_OFF;   K = 384;  N = 1536; nbx = 48; }
    else                 { blk -= 1152; W = w2;    Wt = wh + WH_W2_OFF;   K = 1536; N = 384;  nbx = 12; }
    int bx = blk % nbx, by = blk / nbx;
    int k0 = by * 32, n0 = bx * 32;
    int tx = threadIdx.x, ty = threadIdx.y;
    #pragma unroll
    for (int i = 0; i < 4; i++)
        tile[ty + 8 * i][tx] = W[(size_t)(k0 + ty + 8 * i) * N + n0 + tx];
    __syncthreads();
    #pragma unroll
    for (int i = 0; i < 4; i++)
        Wt[(size_t)(n0 + ty + 8 * i) * K + k0 + tx] = __float2half(tile[tx][ty + 8 * i]);
}

// ---------------- kernel 1: depthwise conv 3x3 + pos bias, coalesced --------
// grid (12 c-groups, 32 h-rows, 16 b), block (32, 8).
// Reads x rows coalesced; writes t with c contiguous (coalesced 128B lines).
__global__ void conv_prep_kernel(const float* __restrict__ x,
                                 const float* __restrict__ pw,
                                 const float* __restrict__ pb,
                                 float* __restrict__ t) {
    __shared__ float xs[32][96];   // [c][row*32 + w], rows h-1,h,h+1
    __shared__ float os[32][33];   // [c][w] conv output tile (padded)
    int cg = blockIdx.x;           // channel group (32 channels)
    int h  = blockIdx.y;
    int b  = blockIdx.z;
    int tx = threadIdx.x;          // w (load/compute) or c (store)
    int ty = threadIdx.y;

    #pragma unroll
    for (int i = 0; i < 4; i++) {
        int c = ty + 8 * i;
        const float* xc = x + (((size_t)(b * CC + cg * 32 + c)) << 10);
        #pragma unroll
        for (int r = 0; r < 3; r++) {
            int hh = h - 1 + r;
            float v = 0.f;
            if (hh >= 0 && hh < 32) v = xc[hh * 32 + tx];
            xs[c][r * 32 + tx] = v;
        }
    }
    __syncthreads();

    #pragma unroll
    for (int i = 0; i < 4; i++) {
        int c = ty + 8 * i;
        const float* k = pw + (cg * 32 + c) * 9;
        float acc = 0.f;
        #pragma unroll
        for (int r = 0; r < 3; r++) {
            #pragma unroll
            for (int dw = -1; dw <= 1; dw++) {
                int ww = tx + dw;
                if (ww >= 0 && ww < 32)
                    acc += xs[c][r * 32 + ww] * k[r * 3 + dw + 1];
            }
        }
        os[c][tx] = xs[c][32 + tx] + acc + pb[cg * 32 + c];
    }
    __syncthreads();

    // write: w = ty+8i, c = tx (consecutive lanes -> consecutive channels)
    #pragma unroll
    for (int i = 0; i < 4; i++) {
        int w = ty + 8 * i;
        t[(size_t)(b * NTOK + h * 32 + w) * CC + cg * 32 + tx] = os[tx][w];
    }
}

// ---------------- kernel 2: LayerNorm -> half output ------------------------
__global__ void ln_kernel(const float* __restrict__ in,
                          const float* __restrict__ g,
                          const float* __restrict__ bta,
                          __half* __restrict__ out) {
    int warp = threadIdx.x >> 5;
    int lane = threadIdx.x & 31;
    int row  = blockIdx.x * 8 + warp;
    const float4* ip = (const float4*)(in + (size_t)row * CC);
    float4 v[3];
    #pragma unroll
    for (int i = 0; i < 3; i++) v[i] = ip[lane + 32 * i];
    float s = 0.f;
    #pragma unroll
    for (int i = 0; i < 3; i++) s += v[i].x + v[i].y + v[i].z + v[i].w;
    #pragma unroll
    for (int o = 16; o; o >>= 1) s += __shfl_xor_sync(0xffffffffu, s, o);
    float mu = s * (1.0f / CC);
    float q = 0.f;
    #pragma unroll
    for (int i = 0; i < 3; i++) {
        float a = v[i].x - mu, b2 = v[i].y - mu, c2 = v[i].z - mu, d2 = v[i].w - mu;
        q += a * a + b2 * b2 + c2 * c2 + d2 * d2;
    }
    #pragma unroll
    for (int o = 16; o; o >>= 1) q += __shfl_xor_sync(0xffffffffu, q, o);
    float r = rsqrtf(q * (1.0f / CC) + 1e-5f);
    __half* op = out + (size_t)row * CC;
    const float4* gp = (const float4*)g;
    const float4* bp = (const float4*)bta;
    #pragma unroll
    for (int i = 0; i < 3; i++) {
        float4 gg = gp[lane + 32 * i];
        float4 bb = bp[lane + 32 * i];
        float o0 = (v[i].x - mu) * r * gg.x + bb.x;
        float o1 = (v[i].y - mu) * r * gg.y + bb.y;
        float o2 = (v[i].z - mu) * r * gg.z + bb.z;
        float o3 = (v[i].w - mu) * r * gg.w + bb.w;
        __half2* dst = (__half2*)(op + 4 * lane + 128 * i);
        dst[0] = __floats2half2_rn(o0, o1);
        dst[1] = __floats2half2_rn(o2, o3);
    }
}

// ---------------- kernel 3: fp16 mma.sync GEMM, ldmatrix, double buffered ----
#define PADK 40   // halves per smem row; 80B stride -> conflict-free ldmatrix

template<bool RESID, bool GELU, bool OUTH>
__global__ __launch_bounds__(256)
void hgemm_kernel(const __half* __restrict__ A, const __half* __restrict__ Bt,
                  const float* __restrict__ bias, void* __restrict__ Cout,
                  int M, int N, int K) {
    __shared__ __half As[2][128 * PADK];
    __shared__ __half Bs[2][128 * PADK];

    int tid = threadIdx.x;
    int m0 = blockIdx.y * 128;
    int n0 = blockIdx.x * 128;

    int wid  = tid >> 5;
    int lane = tid & 31;
    int wm = (wid >> 1) * 32;
    int wn = (wid & 1) * 64;
    int g  = lane >> 2;
    int t0 = lane & 3;

    int frow = tid >> 1;
    int fc   = (tid & 1) * 2;
    const __half* ApG = A  + (size_t)(m0 + frow) * K + fc * 8;
    const __half* BpG = Bt + (size_t)(n0 + frow) * K + fc * 8;
    uint32_t sa = smem_u32(&As[0][frow * PADK + fc * 8]);
    uint32_t sb = smem_u32(&Bs[0][frow * PADK + fc * 8]);
    const uint32_t bufBytes = 128 * PADK * 2;

    float acc[2][8][4];
    #pragma unroll
    for (int mt = 0; mt < 2; mt++)
        #pragma unroll
        for (int nt = 0; nt < 8; nt++)
            #pragma unroll
            for (int i = 0; i < 4; i++) acc[mt][nt][i] = 0.f;

    int nkt = K >> 5;

    cp_async16(sa, ApG);
    cp_async16(sa + 16, ApG + 8);
    cp_async16(sb, BpG);
    cp_async16(sb + 16, BpG + 8);
    CP_COMMIT();

    uint32_t aOff = (uint32_t)((wm + (lane & 15)) * PADK + ((lane >> 4) & 1) * 8) * 2;
    uint32_t bOff = (uint32_t)((wn + (lane & 7) + ((lane >> 4) & 1) * 8) * PADK +
                               ((lane >> 3) & 1) * 8) * 2;
    uint32_t aBase0 = smem_u32(&As[0][0]);
    uint32_t bBase0 = smem_u32(&Bs[0][0]);

    for (int kt = 0; kt < nkt; kt++) {
        int buf = kt & 1;
        if (kt + 1 < nkt) {
            int nb = 1 - buf;
            const __half* Ap = ApG + (kt + 1) * 32;
            const __half* Bp = BpG + (kt + 1) * 32;
            cp_async16(sa + nb * bufBytes, Ap);
            cp_async16(sa + nb * bufBytes + 16, Ap + 8);
            cp_async16(sb + nb * bufBytes, Bp);
            cp_async16(sb + nb * bufBytes + 16, Bp + 8);
            CP_COMMIT();
            CP_WAIT(1);
        } else {
            CP_WAIT(0);
        }
        __syncthreads();

        uint32_t aB = aBase0 + buf * bufBytes + aOff;
        uint32_t bB = bBase0 + buf * bufBytes + bOff;

        #pragma unroll
        for (int kk = 0; kk < 32; kk += 16) {
            uint32_t a[2][4];
            #pragma unroll
            for (int mt = 0; mt < 2; mt++)
                ldmx4(a[mt], aB + (uint32_t)(mt * 16 * PADK + kk) * 2);
            #pragma unroll
            for (int ntp = 0; ntp < 4; ntp++) {
                uint32_t b[4];
                ldmx4(b, bB + (uint32_t)(ntp * 16 * PADK + kk) * 2);
                mma_f16(acc[0][2 * ntp + 0], a[0], b[0], b[1]);
                mma_f16(acc[1][2 * ntp + 0], a[1], b[0], b[1]);
                mma_f16(acc[0][2 * ntp + 1], a[0], b[2], b[3]);
                mma_f16(acc[1][2 * ntp + 1], a[1], b[2], b[3]);
            }
        }
        __syncthreads();
    }

    #pragma unroll
    for (int mt = 0; mt < 2; mt++) {
        #pragma unroll
        for (int nt = 0; nt < 8; nt++) {
            int row = m0 + wm + mt * 16 + g;
            int col = n0 + wn + nt * 8 + 2 * t0;
            float2 bs = *(const float2*)(bias + col);
            float v0 = acc[mt][nt][0] + bs.x;
            float v1 = acc[mt][nt][1] + bs.y;
            float v2 = acc[mt][nt][2] + bs.x;
            float v3 = acc[mt][nt][3] + bs.y;
            if (GELU) {
                v0 = gelu_exact(v0); v1 = gelu_exact(v1);
                v2 = gelu_exact(v2); v3 = gelu_exact(v3);
            }
            if (OUTH) {
                __half* ch = (__half*)Cout;
                *(__half2*)(ch + (size_t)row * N + col)       = __floats2half2_rn(v0, v1);
                *(__half2*)(ch + (size_t)(row + 8) * N + col) = __floats2half2_rn(v2, v3);
            } else {
                float* cf = (float*)Cout;
                float* cp0 = cf + (size_t)row * N + col;
                float* cp1 = cf + (size_t)(row + 8) * N + col;
                if (RESID) {
                    float2 o0 = *(const float2*)cp0;
                    float2 o1 = *(const float2*)cp1;
                    v0 += o0.x; v1 += o0.y; v2 += o1.x; v3 += o1.y;
                }
                *(float2*)cp0 = make_float2(v0, v1);
                *(float2*)cp1 = make_float2(v2, v3);
            }
        }
    }
}

// ---------------- kernel 4: fp16 mma flash attention -------------------------
// 256 threads (8 warps), 128 q-rows/CTA (16 per warp), kv tiles of 64.
#define PADA 56   // 48 + 8 halves; 112B row stride -> conflict-free ldmatrix

__global__ __launch_bounds__(256)
void attn_mma_kernel(const __half* __restrict__ qkv, __half* __restrict__ oh) {
    __shared__ __half Qs[128 * PADA];
    __shared__ __half Ks[64 * PADA];
    __shared__ __half Vs[64 * PADA];

    int tid  = threadIdx.x;
    int wid  = tid >> 5;
    int lane = tid & 31;
    int g    = lane >> 2;
    int t0   = lane & 3;
    int bh   = blockIdx.y;
    int b    = bh >> 3, h = bh & 7;
    int q0   = blockIdx.x * 128;
    const float scale = 0.14433756729740643f; // 48^-0.5

    const __half* qbase = qkv + (size_t)(b * NTOK) * (3 * CC) + h * DH;

    // load Q tile (128 rows x 48 halves): 768 16B chunks, 3/thread
    {
        uint32_t qs = smem_u32(Qs);
        #pragma unroll
        for (int i = 0; i < 3; i++) {
            int chunk = tid * 3 + i;
            int r = chunk / 6, c = chunk % 6;
            cp_async16(qs + (uint32_t)(r * PADA + c * 8) * 2,
                       qbase + (size_t)(q0 + r) * (3 * CC) + c * 8);
        }
        CP_COMMIT();
    }

    float m_r[2] = {-1e30f, -1e30f};
    float l_r[2] = {0.f, 0.f};
    float accO[6][4];
    #pragma unroll
    for (int nt = 0; nt < 6; nt++)
        #pragma unroll
        for (int i = 0; i < 4; i++) accO[nt][i] = 0.f;

    uint32_t qaOff = (uint32_t)((wid * 16 + (lane & 15)) * PADA + ((lane >> 4) & 1) * 8) * 2;
    uint32_t kbOff = (uint32_t)(((lane & 7) + ((lane >> 4) & 1) * 8) * PADA +
                                ((lane >> 3) & 1) * 8) * 2;
    uint32_t vtOff = (uint32_t)(((lane & 7) + ((lane >> 3) & 1) * 8) * PADA +
                                ((lane >> 4) & 1) * 8) * 2;
    uint32_t qB = smem_u32(Qs) + qaOff;
    uint32_t kB = smem_u32(Ks) + kbOff;
    uint32_t vB = smem_u32(Vs) + vtOff;

    CP_WAIT(0);
    __syncthreads();

    uint32_t qf[3][4];
    #pragma unroll
    for (int ks = 0; ks < 3; ks++) ldmx4(qf[ks], qB + (uint32_t)(ks * 16) * 2);

    const __half* kbase = qkv + (size_t)(b * NTOK) * (3 * CC) + CC + h * DH;
    const __half* vbase = kbase + CC;

    for (int kt = 0; kt < 16; kt++) {
        int k0 = kt * 64;
        // load K,V tiles: 768 chunks total (384 K + 384 V), 3/thread
        {
            uint32_t ks = smem_u32(Ks), vs = smem_u32(Vs);
            #pragma unroll
            for (int i = 0; i < 3; i++) {
                int chunk = tid * 3 + i;
                int which = (chunk >= 384);
                int j = which ? chunk - 384 : chunk;
                int r = j / 6, c = j % 6;
                uint32_t dst = (which ? vs : ks) + (uint32_t)(r * PADA + c * 8) * 2;
                const __half* src = (which ? vbase : kbase) + (size_t)(k0 + r) * (3 * CC) + c * 8;
                cp_async16(dst, src);
            }
            CP_COMMIT();
            CP_WAIT(0);
        }
        __syncthreads();

        // S = Q @ K^T : 8 n-tiles of 8 kv each
        float S[8][4];
        #pragma unroll
        for (int nt = 0; nt < 8; nt++)
            #pragma unroll
            for (int i = 0; i < 4; i++) S[nt][i] = 0.f;
        #pragma unroll
        for (int nt16 = 0; nt16 < 4; nt16++) {
            #pragma unroll
            for (int ks = 0; ks < 3; ks++) {
                uint32_t kf[4];
                ldmx4(kf, kB + (uint32_t)(nt16 * 16 * PADA + ks * 16) * 2);
                mma_f16(S[2 * nt16 + 0], qf[ks], kf[0], kf[1]);
                mma_f16(S[2 * nt16 + 1], qf[ks], kf[2], kf[3]);
            }
        }

        // online softmax on fragments (rows g and g+8)
        float tmax0 = -1e30f, tmax1 = -1e30f;
        #pragma unroll
        for (int nt = 0; nt < 8; nt++) {
            #pragma unroll
            for (int i = 0; i < 4; i++) S[nt][i] *= scale;
            tmax0 = fmaxf(tmax0, fmaxf(S[nt][0], S[nt][1]));
            tmax1 = fmaxf(tmax1, fmaxf(S[nt][2], S[nt][3]));
        }
        tmax0 = fmaxf(tmax0, __shfl_xor_sync(0xffffffffu, tmax0, 1));
        tmax0 = fmaxf(tmax0, __shfl_xor_sync(0xffffffffu, tmax0, 2));
        tmax1 = fmaxf(tmax1, __shfl_xor_sync(0xffffffffu, tmax1, 1));
        tmax1 = fmaxf(tmax1, __shfl_xor_sync(0xffffffffu, tmax1, 2));
        float nm0 = fmaxf(m_r[0], tmax0);
        float nm1 = fmaxf(m_r[1], tmax1);
        float al0 = __expf(m_r[0] - nm0);
        float al1 = __expf(m_r[1] - nm1);
        m_r[0] = nm0; m_r[1] = nm1;
        float rs0 = 0.f, rs1 = 0.f;
        #pragma unroll
        for (int nt = 0; nt < 8; nt++) {
            S[nt][0] = __expf(S[nt][0] - nm0);
            S[nt][1] = __expf(S[nt][1] - nm0);
            S[nt][2] = __expf(S[nt][2] - nm1);
            S[nt][3] = __expf(S[nt][3] - nm1);
            rs0 += S[nt][0] + S[nt][1];
            rs1 += S[nt][2] + S[nt][3];
        }
        rs0 += __shfl_xor_sync(0xffffffffu, rs0, 1);
        rs0 += __shfl_xor_sync(0xffffffffu, rs0, 2);
        rs1 += __shfl_xor_sync(0xffffffffu, rs1, 1);
        rs1 += __shfl_xor_sync(0xffffffffu, rs1, 2);
        l_r[0] = l_r[0] * al0 + rs0;
        l_r[1] = l_r[1] * al1 + rs1;
        #pragma unroll
        for (int nt = 0; nt < 6; nt++) {
            accO[nt][0] *= al0; accO[nt][1] *= al0;
            accO[nt][2] *= al1; accO[nt][3] *= al1;
        }

        // P (half) A-fragments from S; O += P @ V
        #pragma unroll
        for (int kb = 0; kb < 4; kb++) {
            uint32_t pa[4];
            pa[0] = pack_h2(S[2 * kb][0],     S[2 * kb][1]);
            pa[1] = pack_h2(S[2 * kb][2],     S[2 * kb][3]);
            pa[2] = pack_h2(S[2 * kb + 1][0], S[2 * kb + 1][1]);
            pa[3] = pack_h2(S[2 * kb + 1][2], S[2 * kb + 1][3]);
            #pragma unroll
            for (int n16 = 0; n16 < 3; n16++) {
                uint32_t vf[4];
                ldmx4t(vf, vB + (uint32_t)(kb * 16 * PADA + n16 * 16) * 2);
                mma_f16(accO[2 * n16 + 0], pa, vf[0], vf[1]);
                mma_f16(accO[2 * n16 + 1], pa, vf[2], vf[3]);
            }
        }
        __syncthreads();
    }

    // write O (half) with 1/l normalization
    float inv0 = 1.f / l_r[0];
    float inv1 = 1.f / l_r[1];
    int row0 = b * NTOK + q0 + wid * 16 + g;
    __half* outp = oh + (size_t)row0 * CC + h * DH + 2 * t0;
    #pragma unroll
    for (int nt = 0; nt < 6; nt++) {
        *(__half2*)(outp + nt * 8) =
            __floats2half2_rn(accO[nt][0] * inv0, accO[nt][1] * inv0);
        *(__half2*)(outp + (size_t)8 * CC + nt * 8) =
            __floats2half2_rn(accO[nt][2] * inv1, accO[nt][3] * inv1);
    }
}

// ---------------- kernel 5: final transpose to NCHW -------------------------
__global__ void transpose_kernel(const float* __restrict__ t, float* __restrict__ out) {
    __shared__ float tile[32][33];
    int b  = blockIdx.z;
    int n0 = blockIdx.x * 32;
    int c0 = blockIdx.y * 32;
    int tx = threadIdx.x, ty = threadIdx.y;
    #pragma unroll
    for (int i = 0; i < 4; i++)
        tile[ty + 8 * i][tx] = t[(size_t)(b * NTOK + n0 + ty + 8 * i) * CC + c0 + tx];
    __syncthreads();
    #pragma unroll
    for (int i = 0; i < 4; i++)
        out[(size_t)(b * CC + c0 + ty + 8 * i) * NTOK + n0 + tx] = tile[tx][ty + 8 * i];
}

// ---------------- launch ----------------------------------------------------
extern "C" void kernel_launch(void* const* d_in, const int* in_sizes, int n_in,
                              void* d_out, int out_size) {
    const float* x     = (const float*)d_in[0];
    const float* pos_w = (const float*)d_in[1];
    const float* pos_b = (const float*)d_in[2];
    const float* g1    = (const float*)d_in[3];
    const float* b1    = (const float*)d_in[4];
    const float* wqkv  = (const float*)d_in[5];
    const float* bqkv  = (const float*)d_in[6];
    const float* wproj = (const float*)d_in[7];
    const float* bproj = (const float*)d_in[8];
    const float* g2    = (const float*)d_in[9];
    const float* b2    = (const float*)d_in[10];
    const float* w1    = (const float*)d_in[11];
    const float* bf1   = (const float*)d_in[12];
    const float* w2    = (const float*)d_in[13];
    const float* bf2   = (const float*)d_in[14];
    float* out = (float*)d_out;

    float *t;
    __half *qkvh, *xh, *ohh, *hh, *wh;
    cudaGetSymbolAddress((void**)&t,    g_t);
    cudaGetSymbolAddress((void**)&qkvh, g_qkvh);
    cudaGetSymbolAddress((void**)&xh,   g_xh);
    cudaGetSymbolAddress((void**)&ohh,  g_oh);
    cudaGetSymbolAddress((void**)&hh,   g_hh);
    cudaGetSymbolAddress((void**)&wh,   g_wh);

    // 0) all weight transposes in one launch
    wtrans_all_kernel<<<1728, dim3(32, 8)>>>(wqkv, wproj, w1, w2, wh);

    // 1) conv + pos bias -> t[m][c] (coalesced writes)
    conv_prep_kernel<<<dim3(CC / 32, 32, BB), dim3(32, 8)>>>(x, pos_w, pos_b, t);

    // 2) LN1: t -> xh (half)
    ln_kernel<<<MTOT / 8, 256>>>(t, g1, b1, xh);
    // 3) qkv = xh @ wqkv + bqkv (half out)
    hgemm_kernel<false, false, true><<<dim3(1152 / 128, MTOT / 128), 256>>>(
        xh, wh + WH_QKV_OFF, bqkv, qkvh, MTOT, 1152, 384);
    // 4) attention (fp16 mma flash, 128 q-rows/CTA) -> oh (half)
    attn_mma_kernel<<<dim3(NTOK / 128, BB * NHEAD), 256>>>(qkvh, ohh);
    // 5) t += oh @ wproj + bproj (fp32 resid)
    hgemm_kernel<true, false, false><<<dim3(384 / 128, MTOT / 128), 256>>>(
        ohh, wh + WH_PROJ_OFF, bproj, t, MTOT, 384, 384);
    // 6) LN2: t -> xh (half)
    ln_kernel<<<MTOT / 8, 256>>>(t, g2, b2, xh);
    // 7) hh = gelu(xh @ w1 + bf1) (half out)
    hgemm_kernel<false, true, true><<<dim3(1536 / 128, MTOT / 128), 256>>>(
        xh, wh + WH_W1_OFF, bf1, hh, MTOT, 1536, 384);
    // 8) t += hh @ w2 + bf2 (fp32 resid)
    hgemm_kernel<true, false, false><<<dim3(384 / 128, MTOT / 128), 256>>>(
        hh, wh + WH_W2_OFF, bf2, t, MTOT, 384, 1536);
    // 9) transpose to NCHW
    transpose_kernel<<<dim3(NTOK / 32, CC / 32, BB), dim3(32, 8)>>>(t, out);
}